// round 4
// baseline (speedup 1.0000x reference)
#include <cuda_runtime.h>
#include <math.h>

// Problem constants
static constexpr int NN   = 100000;   // nodes
static constexpr int NE   = 1600000;  // edges
static constexpr int FIN  = 500;
static constexpr int HID  = 64;
static constexpr int NCLS = 40;

// ---------------- scratch (device globals; no cudaMalloc allowed) ----------
__device__ float g_dinv  [NN];
__device__ float g_h1s   [NN * HID];      // (x@W1) * dinv[row]
__device__ float g_t1    [NN * HID];      // relu(dinv*(agg)+b1)
__device__ float g_gs    [NN * NCLS];     // (h@W2) * dinv[row]
__device__ int   g_src   [NE];
__device__ int   g_dst   [NE];
__device__ int   g_esrc  [NE];            // src ids sorted by dst (CSR payload)
__device__ int   g_cnt   [NN];            // in-degree histogram
__device__ int   g_pos   [NN];            // scatter cursors
__device__ int   g_rowptr[NN + 1];
__device__ int   g_is64;

// ---------------- edge-index dtype detection --------------------------------
__global__ void k_detect(const int* __restrict__ e) {
    if (threadIdx.x == 0 && blockIdx.x == 0) {
        int all0 = 1;
        #pragma unroll 1
        for (int i = 0; i < 64; i++) all0 &= (e[2 * i + 1] == 0);
        g_is64 = all0;
    }
}

__global__ void k_zero() {
    int i = blockIdx.x * blockDim.x + threadIdx.x;
    if (i < NN) { g_cnt[i] = 0; g_pos[i] = 0; }
}

// convert to int32 arrays + build dst histogram
__global__ void k_convert_hist(const int* __restrict__ e) {
    int i = blockIdx.x * blockDim.x + threadIdx.x;
    if (i >= 2 * NE) return;
    int v = g_is64 ? e[2 * i] : e[i];
    if (i < NE) g_src[i] = v;
    else {
        g_dst[i - NE] = v;
        atomicAdd(&g_cnt[v], 1);
    }
}

// single-block exclusive scan of g_cnt -> g_rowptr; also dinv = rsqrt(deg+1)
__global__ __launch_bounds__(1024) void k_scan() {
    __shared__ int ssum[1024];
    const int T = 1024;
    int t = threadIdx.x;
    const int chunk = (NN + T - 1) / T;          // 98
    int lo = t * chunk;
    int hi = lo + chunk; if (hi > NN) hi = NN;

    int s = 0;
    for (int i = lo; i < hi; i++) s += g_cnt[i];
    ssum[t] = s;
    __syncthreads();

    // Hillis-Steele inclusive scan
    for (int off = 1; off < T; off <<= 1) {
        int v = (t >= off) ? ssum[t - off] : 0;
        __syncthreads();
        ssum[t] += v;
        __syncthreads();
    }
    int run = ssum[t] - s;   // exclusive prefix for this thread's chunk
    for (int i = lo; i < hi; i++) {
        int c = g_cnt[i];
        g_rowptr[i] = run;
        run += c;
        g_dinv[i] = rsqrtf((float)c + 1.0f);   // +1 self loop
    }
    if (t == T - 1) g_rowptr[NN] = ssum[T - 1];
}

// scatter: esrc sorted by dst
__global__ void k_scatter() {
    int e = blockIdx.x * blockDim.x + threadIdx.x;
    if (e >= NE) return;
    int d = g_dst[e];
    int p = g_rowptr[d] + atomicAdd(&g_pos[d], 1);
    g_esrc[p] = g_src[e];
}

// ---------------- GEMM1: h1s = (x @ W1) * dinv[row] ------------------------
__global__ __launch_bounds__(256) void k_gemm1(const float* __restrict__ x,
                                               const float* __restrict__ W1) {
    __shared__ float sa[64][33];
    __shared__ float sb[32][64];

    const int tid = threadIdx.x;
    const int tx  = tid & 15;
    const int ty  = tid >> 4;
    const int row0 = blockIdx.x * 64;

    float acc[4][4] = {};

    for (int k0 = 0; k0 < 512; k0 += 32) {
        #pragma unroll
        for (int i = 0; i < 8; i++) {
            int idx = tid + i * 256;
            int r = idx >> 5, c = idx & 31;
            int gr = row0 + r, gc = k0 + c;
            sa[r][c] = (gr < NN && gc < FIN) ? x[(long long)gr * FIN + gc] : 0.f;
        }
        #pragma unroll
        for (int i = 0; i < 8; i++) {
            int idx = tid + i * 256;
            int r = idx >> 6, c = idx & 63;
            int gk = k0 + r;
            sb[r][c] = (gk < FIN) ? W1[gk * HID + c] : 0.f;
        }
        __syncthreads();

        #pragma unroll
        for (int kk = 0; kk < 32; kk++) {
            float av[4], bv[4];
            #pragma unroll
            for (int i = 0; i < 4; i++) av[i] = sa[ty * 4 + i][kk];
            #pragma unroll
            for (int j = 0; j < 4; j++) bv[j] = sb[kk][tx * 4 + j];
            #pragma unroll
            for (int i = 0; i < 4; i++)
                #pragma unroll
                for (int j = 0; j < 4; j++)
                    acc[i][j] += av[i] * bv[j];
        }
        __syncthreads();
    }

    #pragma unroll
    for (int i = 0; i < 4; i++) {
        int r = row0 + ty * 4 + i;
        if (r < NN) {
            float s = g_dinv[r];
            #pragma unroll
            for (int j = 0; j < 4; j++)
                g_h1s[r * HID + tx * 4 + j] = acc[i][j] * s;
        }
    }
}

// ------- Aggregation 1 (CSR, warp/node) + fused relu/bias -> g_t1 ----------
__global__ __launch_bounds__(256) void k_agg1(const float* __restrict__ b1) {
    int node = (int)((blockIdx.x * 256u + threadIdx.x) >> 5);
    int lane = threadIdx.x & 31;
    if (node >= NN) return;

    int beg = g_rowptr[node], end = g_rowptr[node + 1];
    float a0 = g_h1s[node * HID + lane];          // self loop
    float a1 = g_h1s[node * HID + 32 + lane];

    int j = beg;
    for (; j + 3 < end; j += 4) {
        int s0 = g_esrc[j], s1 = g_esrc[j + 1], s2 = g_esrc[j + 2], s3 = g_esrc[j + 3];
        float v00 = g_h1s[s0 * HID + lane],      v01 = g_h1s[s0 * HID + 32 + lane];
        float v10 = g_h1s[s1 * HID + lane],      v11 = g_h1s[s1 * HID + 32 + lane];
        float v20 = g_h1s[s2 * HID + lane],      v21 = g_h1s[s2 * HID + 32 + lane];
        float v30 = g_h1s[s3 * HID + lane],      v31 = g_h1s[s3 * HID + 32 + lane];
        a0 += v00 + v10 + v20 + v30;
        a1 += v01 + v11 + v21 + v31;
    }
    for (; j < end; j++) {
        int s = g_esrc[j];
        a0 += g_h1s[s * HID + lane];
        a1 += g_h1s[s * HID + 32 + lane];
    }

    float dv = g_dinv[node];
    float v0 = dv * a0 + b1[lane];
    float v1 = dv * a1 + b1[32 + lane];
    g_t1[node * HID + lane]      = v0 > 0.f ? v0 : 0.f;
    g_t1[node * HID + 32 + lane] = v1 > 0.f ? v1 : 0.f;
}

// ---------------- GEMM2: gs = (t1 @ W2) * dinv[row] ------------------------
__global__ __launch_bounds__(256) void k_gemm2(const float* __restrict__ W2) {
    __shared__ float sw[HID * NCLS];
    __shared__ float sx[32][65];

    const int tid = threadIdx.x;
    const int row0 = blockIdx.x * 32;

    for (int i = tid; i < HID * NCLS; i += 256) sw[i] = W2[i];
    for (int i = tid; i < 32 * HID; i += 256) {
        int r = i >> 6, c = i & 63;
        int gr = row0 + r;
        sx[r][c] = (gr < NN) ? g_t1[gr * HID + c] : 0.f;
    }
    __syncthreads();

    int r  = tid >> 3;
    int cg = tid & 7;
    float acc[5] = {};
    #pragma unroll
    for (int k = 0; k < HID; k++) {
        float xv = sx[r][k];
        #pragma unroll
        for (int j = 0; j < 5; j++)
            acc[j] += xv * sw[k * NCLS + cg * 5 + j];
    }
    int gr = row0 + r;
    if (gr < NN) {
        float s = g_dinv[gr];
        #pragma unroll
        for (int j = 0; j < 5; j++)
            g_gs[gr * NCLS + cg * 5 + j] = acc[j] * s;
    }
}

// --- Aggregation 2 (CSR, warp/node) + fused bias + log_softmax -> out ------
__global__ __launch_bounds__(256) void k_agg2(const float* __restrict__ b2,
                                              float* __restrict__ out) {
    int node = (int)((blockIdx.x * 256u + threadIdx.x) >> 5);
    int lane = threadIdx.x & 31;
    if (node >= NN) return;

    int beg = g_rowptr[node], end = g_rowptr[node + 1];
    bool hi = lane < (NCLS - 32);     // lanes 0..7 also handle cols 32..39

    float a0 = g_gs[node * NCLS + lane];
    float a1 = hi ? g_gs[node * NCLS + 32 + lane] : 0.f;

    int j = beg;
    for (; j + 1 < end; j += 2) {
        int s0 = g_esrc[j], s1 = g_esrc[j + 1];
        a0 += g_gs[s0 * NCLS + lane] + g_gs[s1 * NCLS + lane];
        if (hi) a1 += g_gs[s0 * NCLS + 32 + lane] + g_gs[s1 * NCLS + 32 + lane];
    }
    for (; j < end; j++) {
        int s = g_esrc[j];
        a0 += g_gs[s * NCLS + lane];
        if (hi) a1 += g_gs[s * NCLS + 32 + lane];
    }

    float dv = g_dinv[node];
    float v0 = dv * a0 + b2[lane];
    float v1 = hi ? (dv * a1 + b2[32 + lane]) : -INFINITY;

    float m = fmaxf(v0, v1);
    #pragma unroll
    for (int o = 16; o; o >>= 1) m = fmaxf(m, __shfl_xor_sync(0xFFFFFFFFu, m, o));

    float e = expf(v0 - m) + (hi ? expf(v1 - m) : 0.f);
    #pragma unroll
    for (int o = 16; o; o >>= 1) e += __shfl_xor_sync(0xFFFFFFFFu, e, o);

    float lse = m + logf(e);
    out[node * NCLS + lane] = v0 - lse;
    if (hi) out[node * NCLS + 32 + lane] = v1 - lse;
}

// ---------------- launch ----------------------------------------------------
extern "C" void kernel_launch(void* const* d_in, const int* in_sizes, int n_in,
                              void* d_out, int out_size) {
    const float* x    = (const float*)d_in[0];
    const float* W1   = (const float*)d_in[1];
    const float* b1   = (const float*)d_in[2];
    const float* W2   = (const float*)d_in[3];
    const float* b2   = (const float*)d_in[4];
    const int*   eraw = (const int*)d_in[5];
    float* out = (float*)d_out;

    (void)in_sizes; (void)n_in; (void)out_size;

    // CSR build
    k_detect      <<<1, 32>>>(eraw);
    k_zero        <<<(NN + 255) / 256, 256>>>();
    k_convert_hist<<<(2 * NE + 255) / 256, 256>>>(eraw);
    k_scan        <<<1, 1024>>>();
    k_scatter     <<<(NE + 255) / 256, 256>>>();

    // layer 1
    k_gemm1<<<(NN + 63) / 64, 256>>>(x, W1);
    k_agg1 <<<(NN * 32 + 255) / 256, 256>>>(b1);

    // layer 2
    k_gemm2<<<(NN + 31) / 32, 256>>>(W2);
    k_agg2 <<<(NN * 32 + 255) / 256, 256>>>(b2, out);
}

// round 5
// speedup vs baseline: 1.4162x; 1.4162x over previous
#include <cuda_runtime.h>
#include <math.h>

// Problem constants
static constexpr int NN   = 100000;   // nodes
static constexpr int NE   = 1600000;  // edges
static constexpr int FIN  = 500;
static constexpr int HID  = 64;
static constexpr int NCLS = 40;

static constexpr int TILE = 512;                       // scan tile
static constexpr int NB   = (NN + TILE - 1) / TILE;    // 196 tiles

// ---------------- scratch (device globals; no cudaMalloc allowed) ----------
__device__ float g_dinv  [NN];
__device__ float g_h1s   [NN * HID];      // (x@W1) * dinv[row]
__device__ float g_t1    [NN * HID];      // relu(dinv*(agg)+b1)
__device__ float g_gs    [NN * NCLS];     // (t1@W2) * dinv[row]
__device__ int   g_esrc  [NE];            // src ids grouped by dst (CSR payload)
__device__ int   g_cnt   [NN];            // in-degree histogram
__device__ int   g_pos   [NN];            // scatter cursors
__device__ int   g_rowptr[NN + 1];
__device__ int   g_bsum  [256];           // tile sums (NB <= 256)
__device__ int   g_boff  [256];           // tile offsets
__device__ int   g_is64;

// ---------------- edge-index dtype detection --------------------------------
__global__ void k_detect(const int* __restrict__ e) {
    if (threadIdx.x == 0 && blockIdx.x == 0) {
        int all0 = 1;
        #pragma unroll 1
        for (int i = 0; i < 64; i++) all0 &= (e[2 * i + 1] == 0);
        g_is64 = all0;
    }
}

__global__ void k_zero() {
    int i = blockIdx.x * blockDim.x + threadIdx.x;
    if (i < NN) { g_cnt[i] = 0; g_pos[i] = 0; }
}

// histogram of dst read straight from raw edge buffer
__global__ void k_hist(const int* __restrict__ e) {
    int i = blockIdx.x * blockDim.x + threadIdx.x;
    if (i >= NE) return;
    int d = g_is64 ? e[2 * (NE + i)] : e[NE + i];
    atomicAdd(&g_cnt[d], 1);
}

// ---- pass 1: per-tile sums --------------------------------------------------
__global__ __launch_bounds__(256) void k_tilesum() {
    __shared__ int sred[256];
    int t = threadIdx.x;
    int base = blockIdx.x * TILE + t * 2;
    int c0 = (base     < NN) ? g_cnt[base]     : 0;
    int c1 = (base + 1 < NN) ? g_cnt[base + 1] : 0;
    sred[t] = c0 + c1;
    __syncthreads();
    #pragma unroll
    for (int o = 128; o; o >>= 1) {
        if (t < o) sred[t] += sred[t + o];
        __syncthreads();
    }
    if (t == 0) g_bsum[blockIdx.x] = sred[0];
}

// ---- pass 2: scan the tile sums (single small block) ------------------------
__global__ __launch_bounds__(256) void k_scanb() {
    __shared__ int s[256];
    int t = threadIdx.x;
    int v = (t < NB) ? g_bsum[t] : 0;
    s[t] = v;
    __syncthreads();
    #pragma unroll
    for (int o = 1; o < 256; o <<= 1) {
        int u = (t >= o) ? s[t - o] : 0;
        __syncthreads();
        s[t] += u;
        __syncthreads();
    }
    g_boff[t] = s[t] - v;                    // exclusive
    if (t == 255) g_rowptr[NN] = s[255];     // total (= NE)
}

// ---- pass 3: per-tile local scan -> rowptr, dinv -----------------------------
__global__ __launch_bounds__(256) void k_rowptr() {
    __shared__ int s[256];
    int t = threadIdx.x;
    int base = blockIdx.x * TILE + t * 2;
    int c0 = (base     < NN) ? g_cnt[base]     : 0;
    int c1 = (base + 1 < NN) ? g_cnt[base + 1] : 0;
    int part = c0 + c1;
    s[t] = part;
    __syncthreads();
    #pragma unroll
    for (int o = 1; o < 256; o <<= 1) {
        int u = (t >= o) ? s[t - o] : 0;
        __syncthreads();
        s[t] += u;
        __syncthreads();
    }
    int pre = g_boff[blockIdx.x] + s[t] - part;   // exclusive prefix for elem base
    if (base < NN) {
        g_rowptr[base] = pre;
        g_dinv[base]   = rsqrtf((float)c0 + 1.0f);
    }
    if (base + 1 < NN) {
        g_rowptr[base + 1] = pre + c0;
        g_dinv[base + 1]   = rsqrtf((float)c1 + 1.0f);
    }
}

// ---- scatter: esrc grouped by dst -------------------------------------------
__global__ void k_scatter(const int* __restrict__ e) {
    int i = blockIdx.x * blockDim.x + threadIdx.x;
    if (i >= NE) return;
    int is64 = g_is64;
    int s = is64 ? e[2 * i]          : e[i];
    int d = is64 ? e[2 * (NE + i)]   : e[NE + i];
    int p = g_rowptr[d] + atomicAdd(&g_pos[d], 1);
    g_esrc[p] = s;
}

// ---------------- GEMM1: h1s = (x @ W1) * dinv[row] ------------------------
__global__ __launch_bounds__(256) void k_gemm1(const float* __restrict__ x,
                                               const float* __restrict__ W1) {
    __shared__ float sa[64][33];
    __shared__ float sb[32][64];

    const int tid = threadIdx.x;
    const int tx  = tid & 15;
    const int ty  = tid >> 4;
    const int row0 = blockIdx.x * 64;

    float acc[4][4] = {};

    for (int k0 = 0; k0 < 512; k0 += 32) {
        #pragma unroll
        for (int i = 0; i < 8; i++) {
            int idx = tid + i * 256;
            int r = idx >> 5, c = idx & 31;
            int gr = row0 + r, gc = k0 + c;
            sa[r][c] = (gr < NN && gc < FIN) ? x[(long long)gr * FIN + gc] : 0.f;
        }
        #pragma unroll
        for (int i = 0; i < 8; i++) {
            int idx = tid + i * 256;
            int r = idx >> 6, c = idx & 63;
            int gk = k0 + r;
            sb[r][c] = (gk < FIN) ? W1[gk * HID + c] : 0.f;
        }
        __syncthreads();

        #pragma unroll
        for (int kk = 0; kk < 32; kk++) {
            float av[4], bv[4];
            #pragma unroll
            for (int i = 0; i < 4; i++) av[i] = sa[ty * 4 + i][kk];
            #pragma unroll
            for (int j = 0; j < 4; j++) bv[j] = sb[kk][tx * 4 + j];
            #pragma unroll
            for (int i = 0; i < 4; i++)
                #pragma unroll
                for (int j = 0; j < 4; j++)
                    acc[i][j] += av[i] * bv[j];
        }
        __syncthreads();
    }

    #pragma unroll
    for (int i = 0; i < 4; i++) {
        int r = row0 + ty * 4 + i;
        if (r < NN) {
            float s = g_dinv[r];
            #pragma unroll
            for (int j = 0; j < 4; j++)
                g_h1s[r * HID + tx * 4 + j] = acc[i][j] * s;
        }
    }
}

// ------- Aggregation 1 (CSR, warp/node) + fused relu/bias -> g_t1 ----------
__global__ __launch_bounds__(256) void k_agg1(const float* __restrict__ b1) {
    int node = (int)((blockIdx.x * 256u + threadIdx.x) >> 5);
    int lane = threadIdx.x & 31;
    if (node >= NN) return;

    int beg = g_rowptr[node], end = g_rowptr[node + 1];
    float a0 = g_h1s[node * HID + lane];          // self loop
    float a1 = g_h1s[node * HID + 32 + lane];

    int j = beg;
    for (; j + 3 < end; j += 4) {
        int s0 = g_esrc[j], s1 = g_esrc[j + 1], s2 = g_esrc[j + 2], s3 = g_esrc[j + 3];
        float v00 = g_h1s[s0 * HID + lane],      v01 = g_h1s[s0 * HID + 32 + lane];
        float v10 = g_h1s[s1 * HID + lane],      v11 = g_h1s[s1 * HID + 32 + lane];
        float v20 = g_h1s[s2 * HID + lane],      v21 = g_h1s[s2 * HID + 32 + lane];
        float v30 = g_h1s[s3 * HID + lane],      v31 = g_h1s[s3 * HID + 32 + lane];
        a0 += v00 + v10 + v20 + v30;
        a1 += v01 + v11 + v21 + v31;
    }
    for (; j < end; j++) {
        int s = g_esrc[j];
        a0 += g_h1s[s * HID + lane];
        a1 += g_h1s[s * HID + 32 + lane];
    }

    float dv = g_dinv[node];
    float v0 = dv * a0 + b1[lane];
    float v1 = dv * a1 + b1[32 + lane];
    g_t1[node * HID + lane]      = v0 > 0.f ? v0 : 0.f;
    g_t1[node * HID + 32 + lane] = v1 > 0.f ? v1 : 0.f;
}

// ---------------- GEMM2: gs = (t1 @ W2) * dinv[row] ------------------------
__global__ __launch_bounds__(256) void k_gemm2(const float* __restrict__ W2) {
    __shared__ float sw[HID * NCLS];
    __shared__ float sx[32][65];

    const int tid = threadIdx.x;
    const int row0 = blockIdx.x * 32;

    for (int i = tid; i < HID * NCLS; i += 256) sw[i] = W2[i];
    for (int i = tid; i < 32 * HID; i += 256) {
        int r = i >> 6, c = i & 63;
        int gr = row0 + r;
        sx[r][c] = (gr < NN) ? g_t1[gr * HID + c] : 0.f;
    }
    __syncthreads();

    int r  = tid >> 3;
    int cg = tid & 7;
    float acc[5] = {};
    #pragma unroll
    for (int k = 0; k < HID; k++) {
        float xv = sx[r][k];
        #pragma unroll
        for (int j = 0; j < 5; j++)
            acc[j] += xv * sw[k * NCLS + cg * 5 + j];
    }
    int gr = row0 + r;
    if (gr < NN) {
        float s = g_dinv[gr];
        #pragma unroll
        for (int j = 0; j < 5; j++)
            g_gs[gr * NCLS + cg * 5 + j] = acc[j] * s;
    }
}

// --- Aggregation 2 (CSR, warp/node) + fused bias + log_softmax -> out ------
__global__ __launch_bounds__(256) void k_agg2(const float* __restrict__ b2,
                                              float* __restrict__ out) {
    int node = (int)((blockIdx.x * 256u + threadIdx.x) >> 5);
    int lane = threadIdx.x & 31;
    if (node >= NN) return;

    int beg = g_rowptr[node], end = g_rowptr[node + 1];
    bool hi = lane < (NCLS - 32);     // lanes 0..7 also handle cols 32..39

    float a0 = g_gs[node * NCLS + lane];
    float a1 = hi ? g_gs[node * NCLS + 32 + lane] : 0.f;

    int j = beg;
    for (; j + 1 < end; j += 2) {
        int s0 = g_esrc[j], s1 = g_esrc[j + 1];
        a0 += g_gs[s0 * NCLS + lane] + g_gs[s1 * NCLS + lane];
        if (hi) a1 += g_gs[s0 * NCLS + 32 + lane] + g_gs[s1 * NCLS + 32 + lane];
    }
    for (; j < end; j++) {
        int s = g_esrc[j];
        a0 += g_gs[s * NCLS + lane];
        if (hi) a1 += g_gs[s * NCLS + 32 + lane];
    }

    float dv = g_dinv[node];
    float v0 = dv * a0 + b2[lane];
    float v1 = hi ? (dv * a1 + b2[32 + lane]) : -INFINITY;

    float m = fmaxf(v0, v1);
    #pragma unroll
    for (int o = 16; o; o >>= 1) m = fmaxf(m, __shfl_xor_sync(0xFFFFFFFFu, m, o));

    float e = expf(v0 - m) + (hi ? expf(v1 - m) : 0.f);
    #pragma unroll
    for (int o = 16; o; o >>= 1) e += __shfl_xor_sync(0xFFFFFFFFu, e, o);

    float lse = m + logf(e);
    out[node * NCLS + lane] = v0 - lse;
    if (hi) out[node * NCLS + 32 + lane] = v1 - lse;
}

// ---------------- launch ----------------------------------------------------
extern "C" void kernel_launch(void* const* d_in, const int* in_sizes, int n_in,
                              void* d_out, int out_size) {
    const float* x    = (const float*)d_in[0];
    const float* W1   = (const float*)d_in[1];
    const float* b1   = (const float*)d_in[2];
    const float* W2   = (const float*)d_in[3];
    const float* b2   = (const float*)d_in[4];
    const int*   eraw = (const int*)d_in[5];
    float* out = (float*)d_out;

    (void)in_sizes; (void)n_in; (void)out_size;

    // CSR build
    k_detect <<<1, 32>>>(eraw);
    k_zero   <<<(NN + 255) / 256, 256>>>();
    k_hist   <<<(NE + 255) / 256, 256>>>(eraw);
    k_tilesum<<<NB, 256>>>();
    k_scanb  <<<1, 256>>>();
    k_rowptr <<<NB, 256>>>();
    k_scatter<<<(NE + 255) / 256, 256>>>(eraw);

    // layer 1
    k_gemm1<<<(NN + 63) / 64, 256>>>(x, W1);
    k_agg1 <<<(NN * 32 + 255) / 256, 256>>>(b1);

    // layer 2
    k_gemm2<<<(NN + 31) / 32, 256>>>(W2);
    k_agg2 <<<(NN * 32 + 255) / 256, 256>>>(b2, out);
}

// round 7
// speedup vs baseline: 1.4588x; 1.0301x over previous
#include <cuda_runtime.h>
#include <cuda_bf16.h>
#include <math.h>
#include <stdint.h>

// Problem constants
static constexpr int NN   = 100000;   // nodes
static constexpr int NE   = 1600000;  // edges
static constexpr int FIN  = 500;
static constexpr int HID  = 64;
static constexpr int NCLS = 40;

static constexpr int TILE = 512;                       // scan tile
static constexpr int NB   = (NN + TILE - 1) / TILE;    // 196 tiles

// ---------------- scratch (device globals; no cudaMalloc allowed) ----------
__device__ float g_dinv  [NN];
__device__ float g_h1s   [NN * HID];      // (x@W1) * dinv[row]
__device__ float g_t1    [NN * HID];      // relu(dinv*(agg)+b1)
__device__ float g_gs    [NN * NCLS];     // (t1@W2) * dinv[row]
__device__ int   g_esrc  [NE];            // src ids grouped by dst (CSR payload)
__device__ int   g_cnt   [NN];            // in-degree histogram
__device__ int   g_pos   [NN];            // scatter cursors
__device__ int   g_rowptr[NN + 1];
__device__ int   g_bsum  [256];
__device__ int   g_boff  [256];
__device__ int   g_is64;

// ---------------- edge-index dtype detection --------------------------------
__global__ void k_detect(const int* __restrict__ e) {
    if (threadIdx.x == 0 && blockIdx.x == 0) {
        int all0 = 1;
        #pragma unroll 1
        for (int i = 0; i < 64; i++) all0 &= (e[2 * i + 1] == 0);
        g_is64 = all0;
    }
}

__global__ void k_zero() {
    int i = blockIdx.x * blockDim.x + threadIdx.x;
    if (i < NN) { g_cnt[i] = 0; g_pos[i] = 0; }
}

__global__ void k_hist(const int* __restrict__ e) {
    int i = blockIdx.x * blockDim.x + threadIdx.x;
    if (i >= NE) return;
    int d = g_is64 ? e[2 * (NE + i)] : e[NE + i];
    atomicAdd(&g_cnt[d], 1);
}

// ---- pass 1: per-tile sums --------------------------------------------------
__global__ __launch_bounds__(256) void k_tilesum() {
    __shared__ int sred[256];
    int t = threadIdx.x;
    int base = blockIdx.x * TILE + t * 2;
    int c0 = (base     < NN) ? g_cnt[base]     : 0;
    int c1 = (base + 1 < NN) ? g_cnt[base + 1] : 0;
    sred[t] = c0 + c1;
    __syncthreads();
    #pragma unroll
    for (int o = 128; o; o >>= 1) {
        if (t < o) sred[t] += sred[t + o];
        __syncthreads();
    }
    if (t == 0) g_bsum[blockIdx.x] = sred[0];
}

// ---- pass 2: scan tile sums ---------------------------------------------------
__global__ __launch_bounds__(256) void k_scanb() {
    __shared__ int s[256];
    int t = threadIdx.x;
    int v = (t < NB) ? g_bsum[t] : 0;
    s[t] = v;
    __syncthreads();
    #pragma unroll
    for (int o = 1; o < 256; o <<= 1) {
        int u = (t >= o) ? s[t - o] : 0;
        __syncthreads();
        s[t] += u;
        __syncthreads();
    }
    g_boff[t] = s[t] - v;
    if (t == 255) g_rowptr[NN] = s[255];
}

// ---- pass 3: per-tile local scan -> rowptr, dinv --------------------------------
__global__ __launch_bounds__(256) void k_rowptr() {
    __shared__ int s[256];
    int t = threadIdx.x;
    int base = blockIdx.x * TILE + t * 2;
    int c0 = (base     < NN) ? g_cnt[base]     : 0;
    int c1 = (base + 1 < NN) ? g_cnt[base + 1] : 0;
    int part = c0 + c1;
    s[t] = part;
    __syncthreads();
    #pragma unroll
    for (int o = 1; o < 256; o <<= 1) {
        int u = (t >= o) ? s[t - o] : 0;
        __syncthreads();
        s[t] += u;
        __syncthreads();
    }
    int pre = g_boff[blockIdx.x] + s[t] - part;
    if (base < NN) {
        g_rowptr[base] = pre;
        g_dinv[base]   = rsqrtf((float)c0 + 1.0f);
    }
    if (base + 1 < NN) {
        g_rowptr[base + 1] = pre + c0;
        g_dinv[base + 1]   = rsqrtf((float)c1 + 1.0f);
    }
}

// ---- scatter: esrc grouped by dst -----------------------------------------------
__global__ void k_scatter(const int* __restrict__ e) {
    int i = blockIdx.x * blockDim.x + threadIdx.x;
    if (i >= NE) return;
    int is64 = g_is64;
    int s = is64 ? e[2 * i]        : e[i];
    int d = is64 ? e[2 * (NE + i)] : e[NE + i];
    int p = g_rowptr[d] + atomicAdd(&g_pos[d], 1);
    g_esrc[p] = s;
}

// ---------------- GEMM1 (mma.sync split-bf16): h1s = (x @ W1) * dinv --------
__device__ __forceinline__ void mma16816(float* c,
                                         uint32_t a0, uint32_t a1, uint32_t a2, uint32_t a3,
                                         uint32_t b0, uint32_t b1) {
    asm volatile(
        "mma.sync.aligned.m16n8k16.row.col.f32.bf16.bf16.f32 "
        "{%0,%1,%2,%3}, {%4,%5,%6,%7}, {%8,%9}, {%0,%1,%2,%3};"
        : "+f"(c[0]), "+f"(c[1]), "+f"(c[2]), "+f"(c[3])
        : "r"(a0), "r"(a1), "r"(a2), "r"(a3), "r"(b0), "r"(b1));
}

// Block tile: 128(M) x 64(N), K-step 32. 8 warps in 4x2; warp tile 32x32.
__global__ __launch_bounds__(256) void k_gemm1_mma(const float* __restrict__ x,
                                                   const float* __restrict__ W1) {
    static constexpr int PA = 40;   // smem pitch in bf16 (pad 32 -> 40; conflict-free)
    __shared__ __nv_bfloat16 sAh[128][PA];
    __shared__ __nv_bfloat16 sAl[128][PA];
    __shared__ __nv_bfloat16 sBh[64][PA];   // [n][k] (col-major B for mma)
    __shared__ __nv_bfloat16 sBl[64][PA];

    const int tid  = threadIdx.x;
    const int wid  = tid >> 5;
    const int lane = tid & 31;
    const int wm   = wid >> 1;           // 0..3  -> M offset wm*32
    const int wn   = wid & 1;            // 0..1  -> N offset wn*32
    const int row0 = blockIdx.x * 128;

    const int lr  = lane >> 2;           // 0..7
    const int lk2 = (lane & 3) * 2;      // 0,2,4,6

    float acc[2][4][4];
    #pragma unroll
    for (int m = 0; m < 2; m++)
        #pragma unroll
        for (int n = 0; n < 4; n++)
            #pragma unroll
            for (int v = 0; v < 4; v++) acc[m][n][v] = 0.f;

    #pragma unroll 1
    for (int k0 = 0; k0 < 512; k0 += 32) {
        // ---- A tile: 128 rows x 32 k, fp32 -> split bf16
        {
            int r = tid >> 1;                       // 0..127
            int q0 = (tid & 1) * 4;                 // float4 quad 0..7
            int gr = row0 + r;
            const float* xr = x + (long long)gr * FIN;
            #pragma unroll
            for (int q = 0; q < 4; q++) {
                int kb = k0 + (q0 + q) * 4;
                float4 v;
                if (gr < NN && kb + 3 < FIN) {
                    v = *(const float4*)(xr + kb);
                } else {
                    v.x = (gr < NN && kb     < FIN) ? xr[kb]     : 0.f;
                    v.y = (gr < NN && kb + 1 < FIN) ? xr[kb + 1] : 0.f;
                    v.z = (gr < NN && kb + 2 < FIN) ? xr[kb + 2] : 0.f;
                    v.w = (gr < NN && kb + 3 < FIN) ? xr[kb + 3] : 0.f;
                }
                int kl = (q0 + q) * 4;
                float vv[4] = {v.x, v.y, v.z, v.w};
                #pragma unroll
                for (int j = 0; j < 4; j++) {
                    __nv_bfloat16 hi = __float2bfloat16(vv[j]);
                    __nv_bfloat16 lo = __float2bfloat16(vv[j] - __bfloat162float(hi));
                    sAh[r][kl + j] = hi;
                    sAl[r][kl + j] = lo;
                }
            }
        }
        // ---- B tile: 32 k x 64 n -> sB[n][k] split bf16
        #pragma unroll
        for (int i = 0; i < 8; i++) {
            int idx = i * 256 + tid;
            int k = idx >> 6, n = idx & 63;
            int gk = k0 + k;
            float wv = (gk < FIN) ? W1[gk * HID + n] : 0.f;
            __nv_bfloat16 hi = __float2bfloat16(wv);
            __nv_bfloat16 lo = __float2bfloat16(wv - __bfloat162float(hi));
            sBh[n][k] = hi;
            sBl[n][k] = lo;
        }
        __syncthreads();

        #pragma unroll
        for (int kt = 0; kt < 2; kt++) {
            const int kk = kt * 16;
            // A fragments for 2 m-tiles (hi & lo)
            uint32_t ah[2][4], al[2][4];
            #pragma unroll
            for (int m = 0; m < 2; m++) {
                int r = wm * 32 + m * 16 + lr;
                ah[m][0] = *(const uint32_t*)&sAh[r][kk + lk2];
                ah[m][1] = *(const uint32_t*)&sAh[r + 8][kk + lk2];
                ah[m][2] = *(const uint32_t*)&sAh[r][kk + 8 + lk2];
                ah[m][3] = *(const uint32_t*)&sAh[r + 8][kk + 8 + lk2];
                al[m][0] = *(const uint32_t*)&sAl[r][kk + lk2];
                al[m][1] = *(const uint32_t*)&sAl[r + 8][kk + lk2];
                al[m][2] = *(const uint32_t*)&sAl[r][kk + 8 + lk2];
                al[m][3] = *(const uint32_t*)&sAl[r + 8][kk + 8 + lk2];
            }
            #pragma unroll
            for (int n = 0; n < 4; n++) {
                int nn = wn * 32 + n * 8 + lr;
                uint32_t bh0 = *(const uint32_t*)&sBh[nn][kk + lk2];
                uint32_t bh1 = *(const uint32_t*)&sBh[nn][kk + 8 + lk2];
                uint32_t bl0 = *(const uint32_t*)&sBl[nn][kk + lk2];
                uint32_t bl1 = *(const uint32_t*)&sBl[nn][kk + 8 + lk2];
                #pragma unroll
                for (int m = 0; m < 2; m++) {
                    mma16816(acc[m][n], ah[m][0], ah[m][1], ah[m][2], ah[m][3], bh0, bh1);
                    mma16816(acc[m][n], ah[m][0], ah[m][1], ah[m][2], ah[m][3], bl0, bl1);
                    mma16816(acc[m][n], al[m][0], al[m][1], al[m][2], al[m][3], bh0, bh1);
                }
            }
        }
        __syncthreads();
    }

    // ---- epilogue: scale by dinv[row], store
    #pragma unroll
    for (int m = 0; m < 2; m++) {
        int r0 = row0 + wm * 32 + m * 16 + lr;
        int r1 = r0 + 8;
        float dv0 = (r0 < NN) ? g_dinv[r0] : 0.f;
        float dv1 = (r1 < NN) ? g_dinv[r1] : 0.f;
        #pragma unroll
        for (int n = 0; n < 4; n++) {
            int c = wn * 32 + n * 8 + lk2;
            if (r0 < NN) {
                g_h1s[r0 * HID + c]     = acc[m][n][0] * dv0;
                g_h1s[r0 * HID + c + 1] = acc[m][n][1] * dv0;
            }
            if (r1 < NN) {
                g_h1s[r1 * HID + c]     = acc[m][n][2] * dv1;
                g_h1s[r1 * HID + c + 1] = acc[m][n][3] * dv1;
            }
        }
    }
}

// ------- Aggregation 1 (CSR, warp/node) + fused relu/bias -> g_t1 ----------
__global__ __launch_bounds__(256) void k_agg1(const float* __restrict__ b1) {
    int node = (int)((blockIdx.x * 256u + threadIdx.x) >> 5);
    int lane = threadIdx.x & 31;
    if (node >= NN) return;

    int beg = g_rowptr[node], end = g_rowptr[node + 1];
    float a0 = g_h1s[node * HID + lane];          // self loop
    float a1 = g_h1s[node * HID + 32 + lane];

    int j = beg;
    for (; j + 3 < end; j += 4) {
        int s0 = g_esrc[j], s1 = g_esrc[j + 1], s2 = g_esrc[j + 2], s3 = g_esrc[j + 3];
        float v00 = g_h1s[s0 * HID + lane],      v01 = g_h1s[s0 * HID + 32 + lane];
        float v10 = g_h1s[s1 * HID + lane],      v11 = g_h1s[s1 * HID + 32 + lane];
        float v20 = g_h1s[s2 * HID + lane],      v21 = g_h1s[s2 * HID + 32 + lane];
        float v30 = g_h1s[s3 * HID + lane],      v31 = g_h1s[s3 * HID + 32 + lane];
        a0 += v00 + v10 + v20 + v30;
        a1 += v01 + v11 + v21 + v31;
    }
    for (; j < end; j++) {
        int s = g_esrc[j];
        a0 += g_h1s[s * HID + lane];
        a1 += g_h1s[s * HID + 32 + lane];
    }

    float dv = g_dinv[node];
    float v0 = dv * a0 + b1[lane];
    float v1 = dv * a1 + b1[32 + lane];
    g_t1[node * HID + lane]      = v0 > 0.f ? v0 : 0.f;
    g_t1[node * HID + 32 + lane] = v1 > 0.f ? v1 : 0.f;
}

// ---------------- GEMM2: gs = (t1 @ W2) * dinv[row] ------------------------
__global__ __launch_bounds__(256) void k_gemm2(const float* __restrict__ W2) {
    __shared__ float sw[HID * NCLS];
    __shared__ float sx[32][65];

    const int tid = threadIdx.x;
    const int row0 = blockIdx.x * 32;

    for (int i = tid; i < HID * NCLS; i += 256) sw[i] = W2[i];
    for (int i = tid; i < 32 * HID; i += 256) {
        int r = i >> 6, c = i & 63;
        int gr = row0 + r;
        sx[r][c] = (gr < NN) ? g_t1[gr * HID + c] : 0.f;
    }
    __syncthreads();

    int r  = tid >> 3;
    int cg = tid & 7;
    float acc[5] = {};
    #pragma unroll
    for (int k = 0; k < HID; k++) {
        float xv = sx[r][k];
        #pragma unroll
        for (int j = 0; j < 5; j++)
            acc[j] += xv * sw[k * NCLS + cg * 5 + j];
    }
    int gr = row0 + r;
    if (gr < NN) {
        float s = g_dinv[gr];
        #pragma unroll
        for (int j = 0; j < 5; j++)
            g_gs[gr * NCLS + cg * 5 + j] = acc[j] * s;
    }
}

// --- Aggregation 2 (CSR, warp/node) + fused bias + log_softmax -> out ------
__global__ __launch_bounds__(256) void k_agg2(const float* __restrict__ b2,
                                              float* __restrict__ out) {
    int node = (int)((blockIdx.x * 256u + threadIdx.x) >> 5);
    int lane = threadIdx.x & 31;
    if (node >= NN) return;

    int beg = g_rowptr[node], end = g_rowptr[node + 1];
    bool hi = lane < (NCLS - 32);

    float a0 = g_gs[node * NCLS + lane];
    float a1 = hi ? g_gs[node * NCLS + 32 + lane] : 0.f;

    int j = beg;
    for (; j + 1 < end; j += 2) {
        int s0 = g_esrc[j], s1 = g_esrc[j + 1];
        a0 += g_gs[s0 * NCLS + lane] + g_gs[s1 * NCLS + lane];
        if (hi) a1 += g_gs[s0 * NCLS + 32 + lane] + g_gs[s1 * NCLS + 32 + lane];
    }
    for (; j < end; j++) {
        int s = g_esrc[j];
        a0 += g_gs[s * NCLS + lane];
        if (hi) a1 += g_gs[s * NCLS + 32 + lane];
    }

    float dv = g_dinv[node];
    float v0 = dv * a0 + b2[lane];
    float v1 = hi ? (dv * a1 + b2[32 + lane]) : -INFINITY;

    float m = fmaxf(v0, v1);
    #pragma unroll
    for (int o = 16; o; o >>= 1) m = fmaxf(m, __shfl_xor_sync(0xFFFFFFFFu, m, o));

    float e = expf(v0 - m) + (hi ? expf(v1 - m) : 0.f);
    #pragma unroll
    for (int o = 16; o; o >>= 1) e += __shfl_xor_sync(0xFFFFFFFFu, e, o);

    float lse = m + logf(e);
    out[node * NCLS + lane] = v0 - lse;
    if (hi) out[node * NCLS + 32 + lane] = v1 - lse;
}

// ---------------- launch ----------------------------------------------------
extern "C" void kernel_launch(void* const* d_in, const int* in_sizes, int n_in,
                              void* d_out, int out_size) {
    const float* x    = (const float*)d_in[0];
    const float* W1   = (const float*)d_in[1];
    const float* b1   = (const float*)d_in[2];
    const float* W2   = (const float*)d_in[3];
    const float* b2   = (const float*)d_in[4];
    const int*   eraw = (const int*)d_in[5];
    float* out = (float*)d_out;

    (void)in_sizes; (void)n_in; (void)out_size;

    // CSR build
    k_detect <<<1, 32>>>(eraw);
    k_zero   <<<(NN + 255) / 256, 256>>>();
    k_hist   <<<(NE + 255) / 256, 256>>>(eraw);
    k_tilesum<<<NB, 256>>>();
    k_scanb  <<<1, 256>>>();
    k_rowptr <<<NB, 256>>>();
    k_scatter<<<(NE + 255) / 256, 256>>>(eraw);

    // layer 1 (tensor-core GEMM via mma.sync, split-bf16)
    k_gemm1_mma<<<(NN + 127) / 128, 256>>>(x, W1);
    k_agg1     <<<(NN * 32 + 255) / 256, 256>>>(b1);

    // layer 2
    k_gemm2<<<(NN + 31) / 32, 256>>>(W2);
    k_agg2 <<<(NN * 32 + 255) / 256, 256>>>(b2, out);
}

// round 8
// speedup vs baseline: 1.8479x; 1.2668x over previous
#include <cuda_runtime.h>
#include <cuda_bf16.h>
#include <math.h>
#include <stdint.h>

// Problem constants
static constexpr int NN   = 100000;   // nodes
static constexpr int NE   = 1600000;  // edges
static constexpr int FIN  = 500;
static constexpr int HID  = 64;
static constexpr int NCLS = 40;

static constexpr int TILE = 512;                       // scan tile
static constexpr int NB   = (NN + TILE - 1) / TILE;    // 196 tiles

// ---------------- scratch (device globals; no cudaMalloc allowed) ----------
__device__ float g_dinv  [NN];
__device__ float g_h1s   [NN * HID];      // x@W1 (raw, no dinv)
__device__ float g_t1    [NN * HID];      // relu(dinv*(agg)+b1)
__device__ float g_gs    [NN * NCLS];     // t1@W2 (raw)
__device__ int   g_esrc  [NE];            // src ids grouped by dst (CSR payload)
__device__ int   g_cnt   [NN];            // in-degree histogram
__device__ int   g_pos   [NN];            // scatter cursors
__device__ int   g_rowptr[NN + 1];
__device__ int   g_bsum  [256];
__device__ int   g_boff  [256];
__device__ int   g_is64;
// W1 pre-converted: [n][kpair] packed bf16x2, k padded to 512 (256 pairs)
__device__ __align__(16) uint32_t g_w1h[64 * 256];
__device__ __align__(16) uint32_t g_w1l[64 * 256];

// ---------------- prep: zero counters, detect dtype, convert W1 -------------
__global__ void k_prep(const int* __restrict__ e, const float* __restrict__ W1) {
    int i = blockIdx.x * blockDim.x + threadIdx.x;
    if (i == 0) {
        int all0 = 1;
        #pragma unroll 1
        for (int j = 0; j < 64; j++) all0 &= (e[2 * j + 1] == 0);
        g_is64 = all0;
    }
    if (i < NN) { g_cnt[i] = 0; g_pos[i] = 0; }
    if (i < 64 * 256) {
        int n = i >> 8, kp = i & 255;
        int k0 = 2 * kp, k1 = 2 * kp + 1;
        float f0 = (k0 < FIN) ? W1[k0 * HID + n] : 0.f;
        float f1 = (k1 < FIN) ? W1[k1 * HID + n] : 0.f;
        uint32_t u0 = __float_as_uint(f0), u1 = __float_as_uint(f1);
        uint32_t hi = __byte_perm(u0, u1, 0x7632);          // {trunc(f0), trunc(f1)}
        float l0 = f0 - __uint_as_float(u0 & 0xFFFF0000u);
        float l1 = f1 - __uint_as_float(u1 & 0xFFFF0000u);
        uint32_t lo;
        asm("cvt.rn.bf16x2.f32 %0, %1, %2;" : "=r"(lo) : "f"(l1), "f"(l0));
        g_w1h[i] = hi;
        g_w1l[i] = lo;
    }
}

__global__ void k_hist(const int* __restrict__ e) {
    int i = blockIdx.x * blockDim.x + threadIdx.x;
    if (i >= NE) return;
    int d = g_is64 ? e[2 * (NE + i)] : e[NE + i];
    atomicAdd(&g_cnt[d], 1);
}

// ---- scan pass 1: per-tile sums ---------------------------------------------
__global__ __launch_bounds__(256) void k_tilesum() {
    __shared__ int sred[256];
    int t = threadIdx.x;
    int base = blockIdx.x * TILE + t * 2;
    int c0 = (base     < NN) ? g_cnt[base]     : 0;
    int c1 = (base + 1 < NN) ? g_cnt[base + 1] : 0;
    sred[t] = c0 + c1;
    __syncthreads();
    #pragma unroll
    for (int o = 128; o; o >>= 1) {
        if (t < o) sred[t] += sred[t + o];
        __syncthreads();
    }
    if (t == 0) g_bsum[blockIdx.x] = sred[0];
}

// ---------------- GEMM1 (mma.sync split-bf16, pipelined): h1s = x @ W1 ------
__device__ __forceinline__ void mma16816(float* c,
                                         uint32_t a0, uint32_t a1, uint32_t a2, uint32_t a3,
                                         uint32_t b0, uint32_t b1) {
    asm volatile(
        "mma.sync.aligned.m16n8k16.row.col.f32.bf16.bf16.f32 "
        "{%0,%1,%2,%3}, {%4,%5,%6,%7}, {%8,%9}, {%0,%1,%2,%3};"
        : "+f"(c[0]), "+f"(c[1]), "+f"(c[2]), "+f"(c[3])
        : "r"(a0), "r"(a1), "r"(a2), "r"(a3), "r"(b0), "r"(b1));
}

// Block tile 128(M) x 64(N), K-step 32, 16 iters. 8 warps 4x2, warp tile 32x32.
__global__ __launch_bounds__(256) void k_gemm1_mma(const float* __restrict__ x) {
    static constexpr int PA = 40;   // bf16 pitch (20 u32)
    __shared__ __align__(16) __nv_bfloat16 sAh[128][PA];
    __shared__ __align__(16) __nv_bfloat16 sAl[128][PA];
    __shared__ __align__(16) __nv_bfloat16 sBh[64][PA];
    __shared__ __align__(16) __nv_bfloat16 sBl[64][PA];
    uint32_t* sAh32 = (uint32_t*)&sAh[0][0];
    uint32_t* sAl32 = (uint32_t*)&sAl[0][0];
    uint32_t* sBh32 = (uint32_t*)&sBh[0][0];
    uint32_t* sBl32 = (uint32_t*)&sBl[0][0];

    const int tid  = threadIdx.x;
    const int wid  = tid >> 5;
    const int lane = tid & 31;
    const int wm   = wid >> 1;
    const int wn   = wid & 1;
    const int row0 = blockIdx.x * 128;

    const int lr  = lane >> 2;
    const int lk2 = (lane & 3) * 2;

    // A loader geometry: row r = tid>>1, 16 consecutive k at (tid&1)*16
    const int ar = tid >> 1;
    const int aq = tid & 1;
    const int gr = row0 + ar;
    const float* xr = x + (long long)gr * FIN;

    // B loader geometry: 1024 u32/tile, 1 uint4 per thread: j = tid*4
    const int bn  = (tid * 4) >> 4;       // 0..63
    const int bkp = (tid * 4) & 15;       // 0,4,8,12

    float acc[2][4][4];
    #pragma unroll
    for (int m = 0; m < 2; m++)
        #pragma unroll
        for (int n = 0; n < 4; n++)
            #pragma unroll
            for (int v = 0; v < 4; v++) acc[m][n][v] = 0.f;

    float4 av[4];
    uint4  bvh, bvl;

    auto loadA = [&](int k0) {
        #pragma unroll
        for (int q4 = 0; q4 < 4; q4++) {
            int kb = k0 + aq * 16 + q4 * 4;
            float4 v;
            if (gr < NN && kb + 3 < FIN) {
                v = *(const float4*)(xr + kb);
            } else {
                v.x = (gr < NN && kb     < FIN) ? xr[kb]     : 0.f;
                v.y = (gr < NN && kb + 1 < FIN) ? xr[kb + 1] : 0.f;
                v.z = (gr < NN && kb + 2 < FIN) ? xr[kb + 2] : 0.f;
                v.w = (gr < NN && kb + 3 < FIN) ? xr[kb + 3] : 0.f;
            }
            av[q4] = v;
        }
    };
    auto loadB = [&](int c) {
        int gidx = bn * 256 + c * 16 + bkp;
        bvh = *(const uint4*)&g_w1h[gidx];
        bvl = *(const uint4*)&g_w1l[gidx];
    };

    loadA(0);
    loadB(0);

    #pragma unroll 1
    for (int c = 0; c < 16; c++) {
        // ---- convert & store A (truncation split, packed) ----
        uint32_t hiP[8], loP[8];
        #pragma unroll
        for (int q4 = 0; q4 < 4; q4++) {
            float f[4] = {av[q4].x, av[q4].y, av[q4].z, av[q4].w};
            #pragma unroll
            for (int p = 0; p < 2; p++) {
                uint32_t u0 = __float_as_uint(f[2 * p]);
                uint32_t u1 = __float_as_uint(f[2 * p + 1]);
                hiP[q4 * 2 + p] = __byte_perm(u0, u1, 0x7632);
                float l0 = f[2 * p]     - __uint_as_float(u0 & 0xFFFF0000u);
                float l1 = f[2 * p + 1] - __uint_as_float(u1 & 0xFFFF0000u);
                asm("cvt.rn.bf16x2.f32 %0, %1, %2;" : "=r"(loP[q4 * 2 + p]) : "f"(l1), "f"(l0));
            }
        }
        {
            uint4* dh = (uint4*)(sAh32 + ar * 20 + aq * 8);
            uint4* dl = (uint4*)(sAl32 + ar * 20 + aq * 8);
            dh[0] = make_uint4(hiP[0], hiP[1], hiP[2], hiP[3]);
            dh[1] = make_uint4(hiP[4], hiP[5], hiP[6], hiP[7]);
            dl[0] = make_uint4(loP[0], loP[1], loP[2], loP[3]);
            dl[1] = make_uint4(loP[4], loP[5], loP[6], loP[7]);
        }
        // ---- store B tile ----
        *(uint4*)(sBh32 + bn * 20 + bkp) = bvh;
        *(uint4*)(sBl32 + bn * 20 + bkp) = bvl;
        __syncthreads();

        // ---- prefetch next tiles (latency overlapped with MMA below) ----
        if (c + 1 < 16) {
            loadA((c + 1) * 32);
            loadB(c + 1);
        }

        #pragma unroll
        for (int kt = 0; kt < 2; kt++) {
            const int kk = kt * 16;
            uint32_t ah[2][4], al[2][4];
            #pragma unroll
            for (int m = 0; m < 2; m++) {
                int r = wm * 32 + m * 16 + lr;
                ah[m][0] = *(const uint32_t*)&sAh[r][kk + lk2];
                ah[m][1] = *(const uint32_t*)&sAh[r + 8][kk + lk2];
                ah[m][2] = *(const uint32_t*)&sAh[r][kk + 8 + lk2];
                ah[m][3] = *(const uint32_t*)&sAh[r + 8][kk + 8 + lk2];
                al[m][0] = *(const uint32_t*)&sAl[r][kk + lk2];
                al[m][1] = *(const uint32_t*)&sAl[r + 8][kk + lk2];
                al[m][2] = *(const uint32_t*)&sAl[r][kk + 8 + lk2];
                al[m][3] = *(const uint32_t*)&sAl[r + 8][kk + 8 + lk2];
            }
            #pragma unroll
            for (int n = 0; n < 4; n++) {
                int nn = wn * 32 + n * 8 + lr;
                uint32_t bh0 = *(const uint32_t*)&sBh[nn][kk + lk2];
                uint32_t bh1 = *(const uint32_t*)&sBh[nn][kk + 8 + lk2];
                uint32_t bl0 = *(const uint32_t*)&sBl[nn][kk + lk2];
                uint32_t bl1 = *(const uint32_t*)&sBl[nn][kk + 8 + lk2];
                #pragma unroll
                for (int m = 0; m < 2; m++) {
                    mma16816(acc[m][n], ah[m][0], ah[m][1], ah[m][2], ah[m][3], bh0, bh1);
                    mma16816(acc[m][n], ah[m][0], ah[m][1], ah[m][2], ah[m][3], bl0, bl1);
                    mma16816(acc[m][n], al[m][0], al[m][1], al[m][2], al[m][3], bh0, bh1);
                }
            }
        }
        __syncthreads();
    }

    // ---- epilogue: store raw h1 ----
    #pragma unroll
    for (int m = 0; m < 2; m++) {
        int r0 = row0 + wm * 32 + m * 16 + lr;
        int r1 = r0 + 8;
        #pragma unroll
        for (int n = 0; n < 4; n++) {
            int cc = wn * 32 + n * 8 + lk2;
            if (r0 < NN) {
                g_h1s[r0 * HID + cc]     = acc[m][n][0];
                g_h1s[r0 * HID + cc + 1] = acc[m][n][1];
            }
            if (r1 < NN) {
                g_h1s[r1 * HID + cc]     = acc[m][n][2];
                g_h1s[r1 * HID + cc + 1] = acc[m][n][3];
            }
        }
    }
}

// ---- scan pass 2 ---------------------------------------------------------------
__global__ __launch_bounds__(256) void k_scanb() {
    __shared__ int s[256];
    int t = threadIdx.x;
    int v = (t < NB) ? g_bsum[t] : 0;
    s[t] = v;
    __syncthreads();
    #pragma unroll
    for (int o = 1; o < 256; o <<= 1) {
        int u = (t >= o) ? s[t - o] : 0;
        __syncthreads();
        s[t] += u;
        __syncthreads();
    }
    g_boff[t] = s[t] - v;
    if (t == 255) g_rowptr[NN] = s[255];
}

// ---- scan pass 3: rowptr + dinv --------------------------------------------------
__global__ __launch_bounds__(256) void k_rowptr() {
    __shared__ int s[256];
    int t = threadIdx.x;
    int base = blockIdx.x * TILE + t * 2;
    int c0 = (base     < NN) ? g_cnt[base]     : 0;
    int c1 = (base + 1 < NN) ? g_cnt[base + 1] : 0;
    int part = c0 + c1;
    s[t] = part;
    __syncthreads();
    #pragma unroll
    for (int o = 1; o < 256; o <<= 1) {
        int u = (t >= o) ? s[t - o] : 0;
        __syncthreads();
        s[t] += u;
        __syncthreads();
    }
    int pre = g_boff[blockIdx.x] + s[t] - part;
    if (base < NN) {
        g_rowptr[base] = pre;
        g_dinv[base]   = rsqrtf((float)c0 + 1.0f);
    }
    if (base + 1 < NN) {
        g_rowptr[base + 1] = pre + c0;
        g_dinv[base + 1]   = rsqrtf((float)c1 + 1.0f);
    }
}

__global__ void k_scatter(const int* __restrict__ e) {
    int i = blockIdx.x * blockDim.x + threadIdx.x;
    if (i >= NE) return;
    int is64 = g_is64;
    int s = is64 ? e[2 * i]        : e[i];
    int d = is64 ? e[2 * (NE + i)] : e[NE + i];
    int p = g_rowptr[d] + atomicAdd(&g_pos[d], 1);
    g_esrc[p] = s;
}

// ------- Aggregation 1 (CSR, warp/node, float2) + relu/bias -> g_t1 ----------
__global__ __launch_bounds__(256) void k_agg1(const float* __restrict__ b1) {
    int node = (int)((blockIdx.x * 256u + threadIdx.x) >> 5);
    int lane = threadIdx.x & 31;
    if (node >= NN) return;

    const float2* H = (const float2*)g_h1s;
    int beg = g_rowptr[node], end = g_rowptr[node + 1];
    float dn = g_dinv[node];

    float2 h0 = H[node * 32 + lane];
    float ax = h0.x * dn, ay = h0.y * dn;   // self loop: h*dinv[node]

    int j = beg;
    for (; j + 1 < end; j += 2) {
        int s0 = g_esrc[j], s1 = g_esrc[j + 1];
        float d0 = g_dinv[s0], d1 = g_dinv[s1];
        float2 v0 = H[s0 * 32 + lane];
        float2 v1 = H[s1 * 32 + lane];
        ax += v0.x * d0 + v1.x * d1;
        ay += v0.y * d0 + v1.y * d1;
    }
    if (j < end) {
        int s = g_esrc[j];
        float ds = g_dinv[s];
        float2 v = H[s * 32 + lane];
        ax += v.x * ds;
        ay += v.y * ds;
    }

    float2 bb = ((const float2*)b1)[lane];
    float vx = dn * ax + bb.x;
    float vy = dn * ay + bb.y;
    float2 o;
    o.x = vx > 0.f ? vx : 0.f;
    o.y = vy > 0.f ? vy : 0.f;
    ((float2*)g_t1)[node * 32 + lane] = o;
}

// ---------------- GEMM2: gs = t1 @ W2 (raw) ---------------------------------
__global__ __launch_bounds__(256) void k_gemm2(const float* __restrict__ W2) {
    __shared__ float sw[HID * NCLS];
    __shared__ float sx[32][65];

    const int tid = threadIdx.x;
    const int row0 = blockIdx.x * 32;

    for (int i = tid; i < HID * NCLS; i += 256) sw[i] = W2[i];
    for (int i = tid; i < 32 * HID; i += 256) {
        int r = i >> 6, c = i & 63;
        int gr = row0 + r;
        sx[r][c] = (gr < NN) ? g_t1[gr * HID + c] : 0.f;
    }
    __syncthreads();

    int r  = tid >> 3;
    int cg = tid & 7;
    float acc[5] = {};
    #pragma unroll
    for (int k = 0; k < HID; k++) {
        float xv = sx[r][k];
        #pragma unroll
        for (int j = 0; j < 5; j++)
            acc[j] += xv * sw[k * NCLS + cg * 5 + j];
    }
    int gr = row0 + r;
    if (gr < NN) {
        #pragma unroll
        for (int j = 0; j < 5; j++)
            g_gs[gr * NCLS + cg * 5 + j] = acc[j];
    }
}

// --- Aggregation 2 (CSR, warp/node, float2) + bias + log_softmax -> out ------
__global__ __launch_bounds__(256) void k_agg2(const float* __restrict__ b2,
                                              float* __restrict__ out) {
    int node = (int)((blockIdx.x * 256u + threadIdx.x) >> 5);
    int lane = threadIdx.x & 31;
    if (node >= NN) return;

    const float2* G = (const float2*)g_gs;
    int beg = g_rowptr[node], end = g_rowptr[node + 1];
    float dn = g_dinv[node];
    bool act = lane < 20;

    float ax = 0.f, ay = 0.f;
    if (act) {
        float2 v = G[node * 20 + lane];
        ax = v.x * dn;
        ay = v.y * dn;
    }

    int j = beg;
    for (; j + 1 < end; j += 2) {
        int s0 = g_esrc[j], s1 = g_esrc[j + 1];
        float d0 = g_dinv[s0], d1 = g_dinv[s1];
        if (act) {
            float2 v0 = G[s0 * 20 + lane];
            float2 v1 = G[s1 * 20 + lane];
            ax += v0.x * d0 + v1.x * d1;
            ay += v0.y * d0 + v1.y * d1;
        }
    }
    if (j < end) {
        int s = g_esrc[j];
        float ds = g_dinv[s];
        if (act) {
            float2 v = G[s * 20 + lane];
            ax += v.x * ds;
            ay += v.y * ds;
        }
    }

    float vx = -INFINITY, vy = -INFINITY;
    if (act) {
        float2 bb = ((const float2*)b2)[lane];
        vx = dn * ax + bb.x;
        vy = dn * ay + bb.y;
    }

    float m = fmaxf(vx, vy);
    #pragma unroll
    for (int o = 16; o; o >>= 1) m = fmaxf(m, __shfl_xor_sync(0xFFFFFFFFu, m, o));

    float e = act ? (expf(vx - m) + expf(vy - m)) : 0.f;
    #pragma unroll
    for (int o = 16; o; o >>= 1) e += __shfl_xor_sync(0xFFFFFFFFu, e, o);

    float lse = m + logf(e);
    if (act) {
        float2 o2;
        o2.x = vx - lse;
        o2.y = vy - lse;
        ((float2*)out)[node * 20 + lane] = o2;
    }
}

// ---------------- launch ----------------------------------------------------
extern "C" void kernel_launch(void* const* d_in, const int* in_sizes, int n_in,
                              void* d_out, int out_size) {
    const float* x    = (const float*)d_in[0];
    const float* W1   = (const float*)d_in[1];
    const float* b1   = (const float*)d_in[2];
    const float* W2   = (const float*)d_in[3];
    const float* b2   = (const float*)d_in[4];
    const int*   eraw = (const int*)d_in[5];
    float* out = (float*)d_out;

    (void)in_sizes; (void)n_in; (void)out_size;

    k_prep     <<<(NN + 255) / 256, 256>>>(eraw, W1);        // 0
    k_hist     <<<(NE + 255) / 256, 256>>>(eraw);            // 1
    k_tilesum  <<<NB, 256>>>();                              // 2
    k_gemm1_mma<<<(NN + 127) / 128, 256>>>(x);               // 3  <- profiled slot
    k_scanb    <<<1, 256>>>();                               // 4
    k_rowptr   <<<NB, 256>>>();                              // 5
    k_scatter  <<<(NE + 255) / 256, 256>>>(eraw);            // 6
    k_agg1     <<<(NN * 32 + 255) / 256, 256>>>(b1);         // 7
    k_gemm2    <<<(NN + 31) / 32, 256>>>(W2);                // 8
    k_agg2     <<<(NN * 32 + 255) / 256, 256>>>(b2, out);    // 9
}

// round 9
// speedup vs baseline: 1.9266x; 1.0425x over previous
#include <cuda_runtime.h>
#include <cuda_bf16.h>
#include <math.h>
#include <stdint.h>

// Problem constants
static constexpr int NN   = 100000;   // nodes
static constexpr int NE   = 1600000;  // edges
static constexpr int FIN  = 500;
static constexpr int HID  = 64;
static constexpr int NCLS = 40;

static constexpr int TILE = 512;                       // scan tile
static constexpr int NB   = (NN + TILE - 1) / TILE;    // 196 tiles

// ---------------- scratch (device globals; no cudaMalloc allowed) ----------
__device__ float g_dinv  [NN];
__device__ float g_h1s   [NN * HID];      // x@W1 (raw, no dinv)
__device__ float g_t1    [NN * HID];      // relu(dinv*(agg)+b1)
__device__ float g_gs    [NN * NCLS];     // t1@W2 (raw)
__device__ int   g_esrc  [NE];            // src ids grouped by dst (CSR payload)
__device__ int   g_cnt   [NN];            // in-degree histogram
__device__ int   g_pos   [NN];            // scatter cursors
__device__ int   g_rowptr[NN + 1];
__device__ int   g_bsum  [256];
__device__ int   g_boff  [256];
__device__ int   g_is64;
// W1 pre-converted: [n][kpair] packed bf16x2, k padded to 512 (256 pairs)
__device__ __align__(16) uint32_t g_w1h[64 * 256];
__device__ __align__(16) uint32_t g_w1l[64 * 256];

// ---------------- prep: zero counters, detect dtype, convert W1 -------------
__global__ void k_prep(const int* __restrict__ e, const float* __restrict__ W1) {
    int i = blockIdx.x * blockDim.x + threadIdx.x;
    if (i == 0) {
        int all0 = 1;
        #pragma unroll 1
        for (int j = 0; j < 64; j++) all0 &= (e[2 * j + 1] == 0);
        g_is64 = all0;
    }
    if (i < NN) { g_cnt[i] = 0; g_pos[i] = 0; }
    if (i < 64 * 256) {
        int n = i >> 8, kp = i & 255;
        int k0 = 2 * kp, k1 = 2 * kp + 1;
        float f0 = (k0 < FIN) ? W1[k0 * HID + n] : 0.f;
        float f1 = (k1 < FIN) ? W1[k1 * HID + n] : 0.f;
        uint32_t u0 = __float_as_uint(f0), u1 = __float_as_uint(f1);
        uint32_t hi = __byte_perm(u0, u1, 0x7632);          // {trunc(f0), trunc(f1)}
        float l0 = f0 - __uint_as_float(u0 & 0xFFFF0000u);
        float l1 = f1 - __uint_as_float(u1 & 0xFFFF0000u);
        uint32_t lo;
        asm("cvt.rn.bf16x2.f32 %0, %1, %2;" : "=r"(lo) : "f"(l1), "f"(l0));
        g_w1h[i] = hi;
        g_w1l[i] = lo;
    }
}

__global__ void k_hist(const int* __restrict__ e) {
    int i = blockIdx.x * blockDim.x + threadIdx.x;
    if (i >= NE) return;
    int d = g_is64 ? e[2 * (NE + i)] : e[NE + i];
    atomicAdd(&g_cnt[d], 1);
}

// ---- scan pass 1: per-tile sums ---------------------------------------------
__global__ __launch_bounds__(256) void k_tilesum() {
    __shared__ int sred[256];
    int t = threadIdx.x;
    int base = blockIdx.x * TILE + t * 2;
    int c0 = (base     < NN) ? g_cnt[base]     : 0;
    int c1 = (base + 1 < NN) ? g_cnt[base + 1] : 0;
    sred[t] = c0 + c1;
    __syncthreads();
    #pragma unroll
    for (int o = 128; o; o >>= 1) {
        if (t < o) sred[t] += sred[t + o];
        __syncthreads();
    }
    if (t == 0) g_bsum[blockIdx.x] = sred[0];
}

// ---------------- GEMM1 (mma.sync split-bf16, double-buffered, ldmatrix) ----
__device__ __forceinline__ void mma16816(float* c,
                                         uint32_t a0, uint32_t a1, uint32_t a2, uint32_t a3,
                                         uint32_t b0, uint32_t b1) {
    asm volatile(
        "mma.sync.aligned.m16n8k16.row.col.f32.bf16.bf16.f32 "
        "{%0,%1,%2,%3}, {%4,%5,%6,%7}, {%8,%9}, {%0,%1,%2,%3};"
        : "+f"(c[0]), "+f"(c[1]), "+f"(c[2]), "+f"(c[3])
        : "r"(a0), "r"(a1), "r"(a2), "r"(a3), "r"(b0), "r"(b1));
}
__device__ __forceinline__ void ldsm4(uint32_t* r, uint32_t addr) {
    asm volatile("ldmatrix.sync.aligned.m8n8.x4.shared.b16 {%0,%1,%2,%3}, [%4];"
                 : "=r"(r[0]), "=r"(r[1]), "=r"(r[2]), "=r"(r[3]) : "r"(addr));
}
__device__ __forceinline__ uint32_t smem_u32(const void* p) {
    uint32_t a;
    asm("{ .reg .u64 t; cvta.to.shared.u64 t, %1; cvt.u32.u64 %0, t; }" : "=r"(a) : "l"(p));
    return a;
}

// SMEM layout (dynamic, 61440 B):
//   AH [2][128][40]bf16 @ 0       (buf stride 10240 B)
//   AL                @ 20480
//   BH [2][64][40]bf16 @ 40960    (buf stride 5120 B)
//   BL                @ 51200
static constexpr int SM_AH = 0;
static constexpr int SM_AL = 20480;
static constexpr int SM_BH = 40960;
static constexpr int SM_BL = 51200;
static constexpr int GEMM1_SMEM = 61440;

// Block tile 128(M) x 64(N), K-step 32, 16 iters. 8 warps 4x2, warp tile 32x32.
__global__ __launch_bounds__(256) void k_gemm1_mma(const float* __restrict__ x) {
    extern __shared__ __align__(16) uint8_t dsm[];
    uint32_t* sm32 = (uint32_t*)dsm;
    const uint32_t smBase = smem_u32(dsm);

    const int tid  = threadIdx.x;
    const int wid  = tid >> 5;
    const int lane = tid & 31;
    const int wm   = wid >> 1;
    const int wn   = wid & 1;
    const int row0 = blockIdx.x * 128;

    // A loader geometry: row ar = tid>>1, 16 consecutive k at aq*16
    const int ar = tid >> 1;
    const int aq = tid & 1;
    const int gr = row0 + ar;
    const float* xr = x + (long long)gr * FIN;

    // B loader geometry: 1024 u32/tile, 1 uint4 per thread
    const int bn  = (tid * 4) >> 4;       // 0..63
    const int bkp = (tid * 4) & 15;       // 0,4,8,12

    // ldmatrix fragment addresses (byte offsets from smBase)
    //   A: row = wm*32 + m*16 + (lane&15), col = (lane>>4)*8 + kt*16
    const uint32_t aOff = (uint32_t)((wm * 32 + (lane & 15)) * 80 + ((lane >> 4) * 8) * 2);
    //   B: row = wn*32 + p*16 + ((lane>>4)&1)*8 + (lane&7), col = ((lane>>3)&1)*8 + kt*16
    const uint32_t bOff = (uint32_t)((wn * 32 + (((lane >> 4) & 1) * 8) + (lane & 7)) * 80
                                     + (((lane >> 3) & 1) * 8) * 2);

    float acc[2][4][4];
    #pragma unroll
    for (int m = 0; m < 2; m++)
        #pragma unroll
        for (int n = 0; n < 4; n++)
            #pragma unroll
            for (int v = 0; v < 4; v++) acc[m][n][v] = 0.f;

    float4 av[4];
    uint4  bvh, bvl;

    auto loadA = [&](int k0) {
        #pragma unroll
        for (int q4 = 0; q4 < 4; q4++) {
            int kb = k0 + aq * 16 + q4 * 4;
            float4 v;
            if (gr < NN && kb + 3 < FIN) {
                v = *(const float4*)(xr + kb);
            } else {
                v.x = (gr < NN && kb     < FIN) ? xr[kb]     : 0.f;
                v.y = (gr < NN && kb + 1 < FIN) ? xr[kb + 1] : 0.f;
                v.z = (gr < NN && kb + 2 < FIN) ? xr[kb + 2] : 0.f;
                v.w = (gr < NN && kb + 3 < FIN) ? xr[kb + 3] : 0.f;
            }
            av[q4] = v;
        }
    };
    auto loadB = [&](int c) {
        int gidx = bn * 256 + c * 16 + bkp;
        bvh = *(const uint4*)&g_w1h[gidx];
        bvl = *(const uint4*)&g_w1l[gidx];
    };
    auto cvtStore = [&](int buf) {
        uint32_t hiP[8], loP[8];
        #pragma unroll
        for (int q4 = 0; q4 < 4; q4++) {
            float f[4] = {av[q4].x, av[q4].y, av[q4].z, av[q4].w};
            #pragma unroll
            for (int p = 0; p < 2; p++) {
                uint32_t u0 = __float_as_uint(f[2 * p]);
                uint32_t u1 = __float_as_uint(f[2 * p + 1]);
                hiP[q4 * 2 + p] = __byte_perm(u0, u1, 0x7632);
                float l0 = f[2 * p]     - __uint_as_float(u0 & 0xFFFF0000u);
                float l1 = f[2 * p + 1] - __uint_as_float(u1 & 0xFFFF0000u);
                asm("cvt.rn.bf16x2.f32 %0, %1, %2;" : "=r"(loP[q4 * 2 + p]) : "f"(l1), "f"(l0));
            }
        }
        uint32_t aIdx = (uint32_t)(buf * 2560 + ar * 20 + aq * 8);
        uint4* dh = (uint4*)(sm32 + (SM_AH >> 2) + aIdx);
        uint4* dl = (uint4*)(sm32 + (SM_AL >> 2) + aIdx);
        dh[0] = make_uint4(hiP[0], hiP[1], hiP[2], hiP[3]);
        dh[1] = make_uint4(hiP[4], hiP[5], hiP[6], hiP[7]);
        dl[0] = make_uint4(loP[0], loP[1], loP[2], loP[3]);
        dl[1] = make_uint4(loP[4], loP[5], loP[6], loP[7]);
        uint32_t bIdx = (uint32_t)(buf * 1280 + bn * 20 + bkp);
        *(uint4*)(sm32 + (SM_BH >> 2) + bIdx) = bvh;
        *(uint4*)(sm32 + (SM_BL >> 2) + bIdx) = bvl;
    };

    // prologue
    loadA(0);
    loadB(0);
    cvtStore(0);

    #pragma unroll 1
    for (int c = 0; c < 16; c++) {
        __syncthreads();
        if (c < 15) {
            loadA((c + 1) * 32);
            loadB(c + 1);
        }
        const int buf = c & 1;
        const uint32_t aH = smBase + SM_AH + buf * 10240 + aOff;
        const uint32_t aL = smBase + SM_AL + buf * 10240 + aOff;
        const uint32_t bH = smBase + SM_BH + buf * 5120 + bOff;
        const uint32_t bL = smBase + SM_BL + buf * 5120 + bOff;

        #pragma unroll
        for (int kt = 0; kt < 2; kt++) {
            const uint32_t ko = kt * 32;
            uint32_t ah[2][4], al[2][4], bh[2][4], bl[2][4];
            #pragma unroll
            for (int m = 0; m < 2; m++) {
                ldsm4(ah[m], aH + m * 1280 + ko);
                ldsm4(al[m], aL + m * 1280 + ko);
            }
            #pragma unroll
            for (int p = 0; p < 2; p++) {
                ldsm4(bh[p], bH + p * 1280 + ko);
                ldsm4(bl[p], bL + p * 1280 + ko);
            }
            #pragma unroll
            for (int n = 0; n < 4; n++) {
                const int p = n >> 1, q = (n & 1) * 2;
                uint32_t bh0 = bh[p][q], bh1 = bh[p][q + 1];
                uint32_t bl0 = bl[p][q], bl1 = bl[p][q + 1];
                #pragma unroll
                for (int m = 0; m < 2; m++) {
                    mma16816(acc[m][n], ah[m][0], ah[m][1], ah[m][2], ah[m][3], bh0, bh1);
                    mma16816(acc[m][n], ah[m][0], ah[m][1], ah[m][2], ah[m][3], bl0, bl1);
                    mma16816(acc[m][n], al[m][0], al[m][1], al[m][2], al[m][3], bh0, bh1);
                }
            }
        }
        if (c < 15) cvtStore((c + 1) & 1);
    }

    // ---- epilogue: store raw h1 ----
    const int lr  = lane >> 2;
    const int lk2 = (lane & 3) * 2;
    #pragma unroll
    for (int m = 0; m < 2; m++) {
        int r0 = row0 + wm * 32 + m * 16 + lr;
        int r1 = r0 + 8;
        #pragma unroll
        for (int n = 0; n < 4; n++) {
            int cc = wn * 32 + n * 8 + lk2;
            if (r0 < NN) {
                g_h1s[r0 * HID + cc]     = acc[m][n][0];
                g_h1s[r0 * HID + cc + 1] = acc[m][n][1];
            }
            if (r1 < NN) {
                g_h1s[r1 * HID + cc]     = acc[m][n][2];
                g_h1s[r1 * HID + cc + 1] = acc[m][n][3];
            }
        }
    }
}

// ---- scan pass 2 ---------------------------------------------------------------
__global__ __launch_bounds__(256) void k_scanb() {
    __shared__ int s[256];
    int t = threadIdx.x;
    int v = (t < NB) ? g_bsum[t] : 0;
    s[t] = v;
    __syncthreads();
    #pragma unroll
    for (int o = 1; o < 256; o <<= 1) {
        int u = (t >= o) ? s[t - o] : 0;
        __syncthreads();
        s[t] += u;
        __syncthreads();
    }
    g_boff[t] = s[t] - v;
    if (t == 255) g_rowptr[NN] = s[255];
}

// ---- scan pass 3: rowptr + dinv --------------------------------------------------
__global__ __launch_bounds__(256) void k_rowptr() {
    __shared__ int s[256];
    int t = threadIdx.x;
    int base = blockIdx.x * TILE + t * 2;
    int c0 = (base     < NN) ? g_cnt[base]     : 0;
    int c1 = (base + 1 < NN) ? g_cnt[base + 1] : 0;
    int part = c0 + c1;
    s[t] = part;
    __syncthreads();
    #pragma unroll
    for (int o = 1; o < 256; o <<= 1) {
        int u = (t >= o) ? s[t - o] : 0;
        __syncthreads();
        s[t] += u;
        __syncthreads();
    }
    int pre = g_boff[blockIdx.x] + s[t] - part;
    if (base < NN) {
        g_rowptr[base] = pre;
        g_dinv[base]   = rsqrtf((float)c0 + 1.0f);
    }
    if (base + 1 < NN) {
        g_rowptr[base + 1] = pre + c0;
        g_dinv[base + 1]   = rsqrtf((float)c1 + 1.0f);
    }
}

__global__ void k_scatter(const int* __restrict__ e) {
    int i = blockIdx.x * blockDim.x + threadIdx.x;
    if (i >= NE) return;
    int is64 = g_is64;
    int s = is64 ? e[2 * i]        : e[i];
    int d = is64 ? e[2 * (NE + i)] : e[NE + i];
    int p = g_rowptr[d] + atomicAdd(&g_pos[d], 1);
    g_esrc[p] = s;
}

// ------- Aggregation 1 (CSR, warp/node, float2) + relu/bias -> g_t1 ----------
__global__ __launch_bounds__(256) void k_agg1(const float* __restrict__ b1) {
    int node = (int)((blockIdx.x * 256u + threadIdx.x) >> 5);
    int lane = threadIdx.x & 31;
    if (node >= NN) return;

    const float2* H = (const float2*)g_h1s;
    int beg = g_rowptr[node], end = g_rowptr[node + 1];
    float dn = g_dinv[node];

    float2 h0 = H[node * 32 + lane];
    float ax = h0.x * dn, ay = h0.y * dn;   // self loop

    int j = beg;
    for (; j + 1 < end; j += 2) {
        int s0 = g_esrc[j], s1 = g_esrc[j + 1];
        float d0 = g_dinv[s0], d1 = g_dinv[s1];
        float2 v0 = H[s0 * 32 + lane];
        float2 v1 = H[s1 * 32 + lane];
        ax += v0.x * d0 + v1.x * d1;
        ay += v0.y * d0 + v1.y * d1;
    }
    if (j < end) {
        int s = g_esrc[j];
        float ds = g_dinv[s];
        float2 v = H[s * 32 + lane];
        ax += v.x * ds;
        ay += v.y * ds;
    }

    float2 bb = ((const float2*)b1)[lane];
    float vx = dn * ax + bb.x;
    float vy = dn * ay + bb.y;
    float2 o;
    o.x = vx > 0.f ? vx : 0.f;
    o.y = vy > 0.f ? vy : 0.f;
    ((float2*)g_t1)[node * 32 + lane] = o;
}

// ---------------- GEMM2: gs = t1 @ W2 (raw) ---------------------------------
__global__ __launch_bounds__(256) void k_gemm2(const float* __restrict__ W2) {
    __shared__ float sw[HID * NCLS];
    __shared__ float sx[32][65];

    const int tid = threadIdx.x;
    const int row0 = blockIdx.x * 32;

    for (int i = tid; i < HID * NCLS; i += 256) sw[i] = W2[i];
    for (int i = tid; i < 32 * HID; i += 256) {
        int r = i >> 6, c = i & 63;
        int gr = row0 + r;
        sx[r][c] = (gr < NN) ? g_t1[gr * HID + c] : 0.f;
    }
    __syncthreads();

    int r  = tid >> 3;
    int cg = tid & 7;
    float acc[5] = {};
    #pragma unroll
    for (int k = 0; k < HID; k++) {
        float xv = sx[r][k];
        #pragma unroll
        for (int j = 0; j < 5; j++)
            acc[j] += xv * sw[k * NCLS + cg * 5 + j];
    }
    int gr = row0 + r;
    if (gr < NN) {
        #pragma unroll
        for (int j = 0; j < 5; j++)
            g_gs[gr * NCLS + cg * 5 + j] = acc[j];
    }
}

// --- Aggregation 2 (CSR, warp/node, float2) + bias + log_softmax -> out ------
__global__ __launch_bounds__(256) void k_agg2(const float* __restrict__ b2,
                                              float* __restrict__ out) {
    int node = (int)((blockIdx.x * 256u + threadIdx.x) >> 5);
    int lane = threadIdx.x & 31;
    if (node >= NN) return;

    const float2* G = (const float2*)g_gs;
    int beg = g_rowptr[node], end = g_rowptr[node + 1];
    float dn = g_dinv[node];
    bool act = lane < 20;

    float ax = 0.f, ay = 0.f;
    if (act) {
        float2 v = G[node * 20 + lane];
        ax = v.x * dn;
        ay = v.y * dn;
    }

    int j = beg;
    for (; j + 1 < end; j += 2) {
        int s0 = g_esrc[j], s1 = g_esrc[j + 1];
        float d0 = g_dinv[s0], d1 = g_dinv[s1];
        if (act) {
            float2 v0 = G[s0 * 20 + lane];
            float2 v1 = G[s1 * 20 + lane];
            ax += v0.x * d0 + v1.x * d1;
            ay += v0.y * d0 + v1.y * d1;
        }
    }
    if (j < end) {
        int s = g_esrc[j];
        float ds = g_dinv[s];
        if (act) {
            float2 v = G[s * 20 + lane];
            ax += v.x * ds;
            ay += v.y * ds;
        }
    }

    float vx = -INFINITY, vy = -INFINITY;
    if (act) {
        float2 bb = ((const float2*)b2)[lane];
        vx = dn * ax + bb.x;
        vy = dn * ay + bb.y;
    }

    float m = fmaxf(vx, vy);
    #pragma unroll
    for (int o = 16; o; o >>= 1) m = fmaxf(m, __shfl_xor_sync(0xFFFFFFFFu, m, o));

    float e = act ? (expf(vx - m) + expf(vy - m)) : 0.f;
    #pragma unroll
    for (int o = 16; o; o >>= 1) e += __shfl_xor_sync(0xFFFFFFFFu, e, o);

    float lse = m + logf(e);
    if (act) {
        float2 o2;
        o2.x = vx - lse;
        o2.y = vy - lse;
        ((float2*)out)[node * 20 + lane] = o2;
    }
}

// ---------------- launch ----------------------------------------------------
extern "C" void kernel_launch(void* const* d_in, const int* in_sizes, int n_in,
                              void* d_out, int out_size) {
    const float* x    = (const float*)d_in[0];
    const float* W1   = (const float*)d_in[1];
    const float* b1   = (const float*)d_in[2];
    const float* W2   = (const float*)d_in[3];
    const float* b2   = (const float*)d_in[4];
    const int*   eraw = (const int*)d_in[5];
    float* out = (float*)d_out;

    (void)in_sizes; (void)n_in; (void)out_size;

    cudaFuncSetAttribute(k_gemm1_mma, cudaFuncAttributeMaxDynamicSharedMemorySize,
                         GEMM1_SMEM);

    k_prep     <<<(NN + 255) / 256, 256>>>(eraw, W1);              // 0
    k_hist     <<<(NE + 255) / 256, 256>>>(eraw);                  // 1
    k_tilesum  <<<NB, 256>>>();                                    // 2
    k_gemm1_mma<<<(NN + 127) / 128, 256, GEMM1_SMEM>>>(x);         // 3  <- profiled slot
    k_scanb    <<<1, 256>>>();                                     // 4
    k_rowptr   <<<NB, 256>>>();                                    // 5
    k_scatter  <<<(NE + 255) / 256, 256>>>(eraw);                  // 6
    k_agg1     <<<(NN * 32 + 255) / 256, 256>>>(b1);               // 7
    k_gemm2    <<<(NN + 31) / 32, 256>>>(W2);                      // 8
    k_agg2     <<<(NN * 32 + 255) / 256, 256>>>(b2, out);          // 9
}

// round 10
// speedup vs baseline: 2.0985x; 1.0893x over previous
#include <cuda_runtime.h>
#include <cuda_bf16.h>
#include <math.h>
#include <stdint.h>

// Problem constants
static constexpr int NN   = 100000;   // nodes
static constexpr int NE   = 1600000;  // edges
static constexpr int FIN  = 500;
static constexpr int HID  = 64;
static constexpr int NCLS = 40;

static constexpr int TILE = 512;                       // scan tile
static constexpr int NB   = (NN + TILE - 1) / TILE;    // 196 tiles

// ---------------- scratch (device globals; no cudaMalloc allowed) ----------
__device__ float g_dinv  [NN];
__device__ float g_h1s   [NN * HID];      // x@W1 (raw, no dinv)
__device__ float g_t1    [NN * HID];      // relu(dinv*(agg)+b1)
__device__ float g_gs    [NN * NCLS];     // t1@W2 (raw)
__device__ int   g_esrc  [NE];            // src ids grouped by dst (CSR payload)
__device__ int   g_cnt   [NN];            // in-degree histogram
__device__ int   g_pos   [NN];            // scatter cursors
__device__ int   g_rowptr[NN + 1];
__device__ int   g_bsum  [256];
__device__ int   g_boff  [256];
__device__ int   g_is64;
// W1 pre-converted: [n][kpair] packed bf16x2, k padded to 512 (256 pairs)
__device__ __align__(16) uint32_t g_w1h[64 * 256];
__device__ __align__(16) uint32_t g_w1l[64 * 256];

// ---------------- prep: zero counters, detect dtype, convert W1 -------------
__global__ void k_prep(const int* __restrict__ e, const float* __restrict__ W1) {
    int i = blockIdx.x * blockDim.x + threadIdx.x;
    if (i == 0) {
        int all0 = 1;
        #pragma unroll 1
        for (int j = 0; j < 64; j++) all0 &= (e[2 * j + 1] == 0);
        g_is64 = all0;
    }
    if (i < NN) { g_cnt[i] = 0; g_pos[i] = 0; }
    if (i < 64 * 256) {
        int n = i >> 8, kp = i & 255;
        int k0 = 2 * kp, k1 = 2 * kp + 1;
        float f0 = (k0 < FIN) ? W1[k0 * HID + n] : 0.f;
        float f1 = (k1 < FIN) ? W1[k1 * HID + n] : 0.f;
        uint32_t u0 = __float_as_uint(f0), u1 = __float_as_uint(f1);
        uint32_t hi = __byte_perm(u0, u1, 0x7632);          // {trunc(f0), trunc(f1)}
        float l0 = f0 - __uint_as_float(u0 & 0xFFFF0000u);
        float l1 = f1 - __uint_as_float(u1 & 0xFFFF0000u);
        uint32_t lo;
        asm("cvt.rn.bf16x2.f32 %0, %1, %2;" : "=r"(lo) : "f"(l1), "f"(l0));
        g_w1h[i] = hi;
        g_w1l[i] = lo;
    }
}

__global__ void k_hist(const int* __restrict__ e) {
    int i = blockIdx.x * blockDim.x + threadIdx.x;
    if (i >= NE) return;
    int d = g_is64 ? e[2 * (NE + i)] : e[NE + i];
    atomicAdd(&g_cnt[d], 1);
}

// ---- scan pass 1: per-tile sums ---------------------------------------------
__global__ __launch_bounds__(256) void k_tilesum() {
    __shared__ int sred[256];
    int t = threadIdx.x;
    int base = blockIdx.x * TILE + t * 2;
    int c0 = (base     < NN) ? g_cnt[base]     : 0;
    int c1 = (base + 1 < NN) ? g_cnt[base + 1] : 0;
    sred[t] = c0 + c1;
    __syncthreads();
    #pragma unroll
    for (int o = 128; o; o >>= 1) {
        if (t < o) sred[t] += sred[t + o];
        __syncthreads();
    }
    if (t == 0) g_bsum[blockIdx.x] = sred[0];
}

// ---------------- GEMM1 (mma.sync split-bf16, double-buffered, ldmatrix) ----
__device__ __forceinline__ void mma16816(float* c,
                                         uint32_t a0, uint32_t a1, uint32_t a2, uint32_t a3,
                                         uint32_t b0, uint32_t b1) {
    asm volatile(
        "mma.sync.aligned.m16n8k16.row.col.f32.bf16.bf16.f32 "
        "{%0,%1,%2,%3}, {%4,%5,%6,%7}, {%8,%9}, {%0,%1,%2,%3};"
        : "+f"(c[0]), "+f"(c[1]), "+f"(c[2]), "+f"(c[3])
        : "r"(a0), "r"(a1), "r"(a2), "r"(a3), "r"(b0), "r"(b1));
}
__device__ __forceinline__ void ldsm4(uint32_t* r, uint32_t addr) {
    asm volatile("ldmatrix.sync.aligned.m8n8.x4.shared.b16 {%0,%1,%2,%3}, [%4];"
                 : "=r"(r[0]), "=r"(r[1]), "=r"(r[2]), "=r"(r[3]) : "r"(addr));
}
__device__ __forceinline__ uint32_t smem_u32(const void* p) {
    uint32_t a;
    asm("{ .reg .u64 t; cvta.to.shared.u64 t, %1; cvt.u32.u64 %0, t; }" : "=r"(a) : "l"(p));
    return a;
}

// SMEM layout (dynamic, 61440 B):
//   AH [2][128][40]bf16 @ 0       (buf stride 10240 B)
//   AL                @ 20480
//   BH [2][64][40]bf16 @ 40960    (buf stride 5120 B)
//   BL                @ 51200
static constexpr int SM_AH = 0;
static constexpr int SM_AL = 20480;
static constexpr int SM_BH = 40960;
static constexpr int SM_BL = 51200;
static constexpr int GEMM1_SMEM = 61440;

// Block tile 128(M) x 64(N), K-step 32, 16 iters. 8 warps 4x2, warp tile 32x32.
__global__ __launch_bounds__(256) void k_gemm1_mma(const float* __restrict__ x) {
    extern __shared__ __align__(16) uint8_t dsm[];
    uint32_t* sm32 = (uint32_t*)dsm;
    const uint32_t smBase = smem_u32(dsm);

    const int tid  = threadIdx.x;
    const int wid  = tid >> 5;
    const int lane = tid & 31;
    const int wm   = wid >> 1;
    const int wn   = wid & 1;
    const int row0 = blockIdx.x * 128;

    // A loader geometry: row ar = tid>>1, 16 consecutive k at aq*16
    const int ar = tid >> 1;
    const int aq = tid & 1;
    const int gr = row0 + ar;
    const float* xr = x + (long long)gr * FIN;

    // B loader geometry: 1024 u32/tile, 1 uint4 per thread
    const int bn  = (tid * 4) >> 4;       // 0..63
    const int bkp = (tid * 4) & 15;       // 0,4,8,12

    // ldmatrix fragment addresses (byte offsets from smBase)
    const uint32_t aOff = (uint32_t)((wm * 32 + (lane & 15)) * 80 + ((lane >> 4) * 8) * 2);
    const uint32_t bOff = (uint32_t)((wn * 32 + (((lane >> 4) & 1) * 8) + (lane & 7)) * 80
                                     + (((lane >> 3) & 1) * 8) * 2);

    float acc[2][4][4];
    #pragma unroll
    for (int m = 0; m < 2; m++)
        #pragma unroll
        for (int n = 0; n < 4; n++)
            #pragma unroll
            for (int v = 0; v < 4; v++) acc[m][n][v] = 0.f;

    float4 av[4];
    uint4  bvh, bvl;

    auto loadA = [&](int k0) {
        #pragma unroll
        for (int q4 = 0; q4 < 4; q4++) {
            int kb = k0 + aq * 16 + q4 * 4;
            float4 v;
            if (gr < NN && kb + 3 < FIN) {
                v = *(const float4*)(xr + kb);
            } else {
                v.x = (gr < NN && kb     < FIN) ? xr[kb]     : 0.f;
                v.y = (gr < NN && kb + 1 < FIN) ? xr[kb + 1] : 0.f;
                v.z = (gr < NN && kb + 2 < FIN) ? xr[kb + 2] : 0.f;
                v.w = (gr < NN && kb + 3 < FIN) ? xr[kb + 3] : 0.f;
            }
            av[q4] = v;
        }
    };
    auto loadB = [&](int c) {
        int gidx = bn * 256 + c * 16 + bkp;
        bvh = *(const uint4*)&g_w1h[gidx];
        bvl = *(const uint4*)&g_w1l[gidx];
    };
    auto cvtStore = [&](int buf) {
        uint32_t hiP[8], loP[8];
        #pragma unroll
        for (int q4 = 0; q4 < 4; q4++) {
            float f[4] = {av[q4].x, av[q4].y, av[q4].z, av[q4].w};
            #pragma unroll
            for (int p = 0; p < 2; p++) {
                uint32_t u0 = __float_as_uint(f[2 * p]);
                uint32_t u1 = __float_as_uint(f[2 * p + 1]);
                hiP[q4 * 2 + p] = __byte_perm(u0, u1, 0x7632);
                float l0 = f[2 * p]     - __uint_as_float(u0 & 0xFFFF0000u);
                float l1 = f[2 * p + 1] - __uint_as_float(u1 & 0xFFFF0000u);
                asm("cvt.rn.bf16x2.f32 %0, %1, %2;" : "=r"(loP[q4 * 2 + p]) : "f"(l1), "f"(l0));
            }
        }
        uint32_t aIdx = (uint32_t)(buf * 2560 + ar * 20 + aq * 8);
        uint4* dh = (uint4*)(sm32 + (SM_AH >> 2) + aIdx);
        uint4* dl = (uint4*)(sm32 + (SM_AL >> 2) + aIdx);
        dh[0] = make_uint4(hiP[0], hiP[1], hiP[2], hiP[3]);
        dh[1] = make_uint4(hiP[4], hiP[5], hiP[6], hiP[7]);
        dl[0] = make_uint4(loP[0], loP[1], loP[2], loP[3]);
        dl[1] = make_uint4(loP[4], loP[5], loP[6], loP[7]);
        uint32_t bIdx = (uint32_t)(buf * 1280 + bn * 20 + bkp);
        *(uint4*)(sm32 + (SM_BH >> 2) + bIdx) = bvh;
        *(uint4*)(sm32 + (SM_BL >> 2) + bIdx) = bvl;
    };

    // prologue
    loadA(0);
    loadB(0);
    cvtStore(0);

    #pragma unroll 1
    for (int c = 0; c < 16; c++) {
        __syncthreads();
        if (c < 15) {
            loadA((c + 1) * 32);
            loadB(c + 1);
        }
        const int buf = c & 1;
        const uint32_t aH = smBase + SM_AH + buf * 10240 + aOff;
        const uint32_t aL = smBase + SM_AL + buf * 10240 + aOff;
        const uint32_t bH = smBase + SM_BH + buf * 5120 + bOff;
        const uint32_t bL = smBase + SM_BL + buf * 5120 + bOff;

        #pragma unroll
        for (int kt = 0; kt < 2; kt++) {
            const uint32_t ko = kt * 32;
            uint32_t ah[2][4], al[2][4], bh[2][4], bl[2][4];
            #pragma unroll
            for (int m = 0; m < 2; m++) {
                ldsm4(ah[m], aH + m * 1280 + ko);
                ldsm4(al[m], aL + m * 1280 + ko);
            }
            #pragma unroll
            for (int p = 0; p < 2; p++) {
                ldsm4(bh[p], bH + p * 1280 + ko);
                ldsm4(bl[p], bL + p * 1280 + ko);
            }
            #pragma unroll
            for (int n = 0; n < 4; n++) {
                const int p = n >> 1, q = (n & 1) * 2;
                uint32_t bh0 = bh[p][q], bh1 = bh[p][q + 1];
                uint32_t bl0 = bl[p][q], bl1 = bl[p][q + 1];
                #pragma unroll
                for (int m = 0; m < 2; m++) {
                    mma16816(acc[m][n], ah[m][0], ah[m][1], ah[m][2], ah[m][3], bh0, bh1);
                    mma16816(acc[m][n], ah[m][0], ah[m][1], ah[m][2], ah[m][3], bl0, bl1);
                    mma16816(acc[m][n], al[m][0], al[m][1], al[m][2], al[m][3], bh0, bh1);
                }
            }
        }
        if (c < 15) cvtStore((c + 1) & 1);
    }

    // ---- epilogue: store raw h1 ----
    const int lr  = lane >> 2;
    const int lk2 = (lane & 3) * 2;
    #pragma unroll
    for (int m = 0; m < 2; m++) {
        int r0 = row0 + wm * 32 + m * 16 + lr;
        int r1 = r0 + 8;
        #pragma unroll
        for (int n = 0; n < 4; n++) {
            int cc = wn * 32 + n * 8 + lk2;
            if (r0 < NN) {
                g_h1s[r0 * HID + cc]     = acc[m][n][0];
                g_h1s[r0 * HID + cc + 1] = acc[m][n][1];
            }
            if (r1 < NN) {
                g_h1s[r1 * HID + cc]     = acc[m][n][2];
                g_h1s[r1 * HID + cc + 1] = acc[m][n][3];
            }
        }
    }
}

// ---- scan pass 2 ---------------------------------------------------------------
__global__ __launch_bounds__(256) void k_scanb() {
    __shared__ int s[256];
    int t = threadIdx.x;
    int v = (t < NB) ? g_bsum[t] : 0;
    s[t] = v;
    __syncthreads();
    #pragma unroll
    for (int o = 1; o < 256; o <<= 1) {
        int u = (t >= o) ? s[t - o] : 0;
        __syncthreads();
        s[t] += u;
        __syncthreads();
    }
    g_boff[t] = s[t] - v;
    if (t == 255) g_rowptr[NN] = s[255];
}

// ---- scan pass 3: rowptr + dinv --------------------------------------------------
__global__ __launch_bounds__(256) void k_rowptr() {
    __shared__ int s[256];
    int t = threadIdx.x;
    int base = blockIdx.x * TILE + t * 2;
    int c0 = (base     < NN) ? g_cnt[base]     : 0;
    int c1 = (base + 1 < NN) ? g_cnt[base + 1] : 0;
    int part = c0 + c1;
    s[t] = part;
    __syncthreads();
    #pragma unroll
    for (int o = 1; o < 256; o <<= 1) {
        int u = (t >= o) ? s[t - o] : 0;
        __syncthreads();
        s[t] += u;
        __syncthreads();
    }
    int pre = g_boff[blockIdx.x] + s[t] - part;
    if (base < NN) {
        g_rowptr[base] = pre;
        g_dinv[base]   = rsqrtf((float)c0 + 1.0f);
    }
    if (base + 1 < NN) {
        g_rowptr[base + 1] = pre + c0;
        g_dinv[base + 1]   = rsqrtf((float)c1 + 1.0f);
    }
}

__global__ void k_scatter(const int* __restrict__ e) {
    int i = blockIdx.x * blockDim.x + threadIdx.x;
    if (i >= NE) return;
    int is64 = g_is64;
    int s = is64 ? e[2 * i]        : e[i];
    int d = is64 ? e[2 * (NE + i)] : e[NE + i];
    int p = g_rowptr[d] + atomicAdd(&g_pos[d], 1);
    g_esrc[p] = s;
}

// ------- Aggregation 1 (CSR, warp/node, float2) + relu/bias -> g_t1 ----------
__global__ __launch_bounds__(256) void k_agg1(const float* __restrict__ b1) {
    int node = (int)((blockIdx.x * 256u + threadIdx.x) >> 5);
    int lane = threadIdx.x & 31;
    if (node >= NN) return;

    const float2* H = (const float2*)g_h1s;
    int beg = g_rowptr[node], end = g_rowptr[node + 1];
    float dn = g_dinv[node];

    float2 h0 = H[node * 32 + lane];
    float ax = h0.x * dn, ay = h0.y * dn;   // self loop

    int j = beg;
    for (; j + 1 < end; j += 2) {
        int s0 = g_esrc[j], s1 = g_esrc[j + 1];
        float d0 = g_dinv[s0], d1 = g_dinv[s1];
        float2 v0 = H[s0 * 32 + lane];
        float2 v1 = H[s1 * 32 + lane];
        ax += v0.x * d0 + v1.x * d1;
        ay += v0.y * d0 + v1.y * d1;
    }
    if (j < end) {
        int s = g_esrc[j];
        float ds = g_dinv[s];
        float2 v = H[s * 32 + lane];
        ax += v.x * ds;
        ay += v.y * ds;
    }

    float2 bb = ((const float2*)b1)[lane];
    float vx = dn * ax + bb.x;
    float vy = dn * ay + bb.y;
    float2 o;
    o.x = vx > 0.f ? vx : 0.f;
    o.y = vy > 0.f ? vy : 0.f;
    ((float2*)g_t1)[node * 32 + lane] = o;
}

// ---------------- GEMM2: gs = t1 @ W2 (raw) ---------------------------------
__global__ __launch_bounds__(256) void k_gemm2(const float* __restrict__ W2) {
    __shared__ float sw[HID * NCLS];
    __shared__ float sx[32][65];

    const int tid = threadIdx.x;
    const int row0 = blockIdx.x * 32;

    for (int i = tid; i < HID * NCLS; i += 256) sw[i] = W2[i];
    for (int i = tid; i < 32 * HID; i += 256) {
        int r = i >> 6, c = i & 63;
        int gr = row0 + r;
        sx[r][c] = (gr < NN) ? g_t1[gr * HID + c] : 0.f;
    }
    __syncthreads();

    int r  = tid >> 3;
    int cg = tid & 7;
    float acc[5] = {};
    #pragma unroll
    for (int k = 0; k < HID; k++) {
        float xv = sx[r][k];
        #pragma unroll
        for (int j = 0; j < 5; j++)
            acc[j] += xv * sw[k * NCLS + cg * 5 + j];
    }
    int gr = row0 + r;
    if (gr < NN) {
        #pragma unroll
        for (int j = 0; j < 5; j++)
            g_gs[gr * NCLS + cg * 5 + j] = acc[j];
    }
}

// --- Aggregation 2 (CSR, warp/node, float2) + bias + log_softmax -> out ------
__global__ __launch_bounds__(256) void k_agg2(const float* __restrict__ b2,
                                              float* __restrict__ out) {
    int node = (int)((blockIdx.x * 256u + threadIdx.x) >> 5);
    int lane = threadIdx.x & 31;
    if (node >= NN) return;

    const float2* G = (const float2*)g_gs;
    int beg = g_rowptr[node], end = g_rowptr[node + 1];
    float dn = g_dinv[node];
    bool act = lane < 20;

    float ax = 0.f, ay = 0.f;
    if (act) {
        float2 v = G[node * 20 + lane];
        ax = v.x * dn;
        ay = v.y * dn;
    }

    int j = beg;
    for (; j + 1 < end; j += 2) {
        int s0 = g_esrc[j], s1 = g_esrc[j + 1];
        float d0 = g_dinv[s0], d1 = g_dinv[s1];
        if (act) {
            float2 v0 = G[s0 * 20 + lane];
            float2 v1 = G[s1 * 20 + lane];
            ax += v0.x * d0 + v1.x * d1;
            ay += v0.y * d0 + v1.y * d1;
        }
    }
    if (j < end) {
        int s = g_esrc[j];
        float ds = g_dinv[s];
        if (act) {
            float2 v = G[s * 20 + lane];
            ax += v.x * ds;
            ay += v.y * ds;
        }
    }

    float vx = -INFINITY, vy = -INFINITY;
    if (act) {
        float2 bb = ((const float2*)b2)[lane];
        vx = dn * ax + bb.x;
        vy = dn * ay + bb.y;
    }

    float m = fmaxf(vx, vy);
    #pragma unroll
    for (int o = 16; o; o >>= 1) m = fmaxf(m, __shfl_xor_sync(0xFFFFFFFFu, m, o));

    float e = act ? (expf(vx - m) + expf(vy - m)) : 0.f;
    #pragma unroll
    for (int o = 16; o; o >>= 1) e += __shfl_xor_sync(0xFFFFFFFFu, e, o);

    float lse = m + logf(e);
    if (act) {
        float2 o2;
        o2.x = vx - lse;
        o2.y = vy - lse;
        ((float2*)out)[node * 20 + lane] = o2;
    }
}

// ---------------- launch ----------------------------------------------------
extern "C" void kernel_launch(void* const* d_in, const int* in_sizes, int n_in,
                              void* d_out, int out_size) {
    const float* x    = (const float*)d_in[0];
    const float* W1   = (const float*)d_in[1];
    const float* b1   = (const float*)d_in[2];
    const float* W2   = (const float*)d_in[3];
    const float* b2   = (const float*)d_in[4];
    const int*   eraw = (const int*)d_in[5];
    float* out = (float*)d_out;

    (void)in_sizes; (void)n_in; (void)out_size;

    // one-time host-side resources (no device memory allocation)
    static cudaStream_t s_side = nullptr;
    static cudaEvent_t ev_fork = nullptr, ev_join = nullptr;
    static bool init_done = false;
    if (!init_done) {
        cudaStreamCreateWithFlags(&s_side, cudaStreamNonBlocking);
        cudaEventCreateWithFlags(&ev_fork, cudaEventDisableTiming);
        cudaEventCreateWithFlags(&ev_join, cudaEventDisableTiming);
        cudaFuncSetAttribute(k_gemm1_mma, cudaFuncAttributeMaxDynamicSharedMemorySize,
                             GEMM1_SMEM);
        init_done = true;
    }

    // main stream: prep, then fork
    k_prep<<<(NN + 255) / 256, 256>>>(eraw, W1);
    cudaEventRecord(ev_fork, 0);
    cudaStreamWaitEvent(s_side, ev_fork, 0);

    // main stream: tensor-core GEMM1 (concurrent with CSR build)
    k_gemm1_mma<<<(NN + 127) / 128, 256, GEMM1_SMEM>>>(x);

    // side stream: CSR build
    k_hist   <<<(NE + 255) / 256, 256, 0, s_side>>>(eraw);
    k_tilesum<<<NB, 256, 0, s_side>>>();
    k_scanb  <<<1, 256, 0, s_side>>>();
    k_rowptr <<<NB, 256, 0, s_side>>>();
    k_scatter<<<(NE + 255) / 256, 256, 0, s_side>>>(eraw);
    cudaEventRecord(ev_join, s_side);

    // join, then the dependent tail on the main stream
    cudaStreamWaitEvent(0, ev_join, 0);
    k_agg1 <<<(NN * 32 + 255) / 256, 256>>>(b1);
    k_gemm2<<<(NN + 31) / 32, 256>>>(W2);
    k_agg2 <<<(NN * 32 + 255) / 256, 256>>>(b2, out);
}